// round 7
// baseline (speedup 1.0000x reference)
#include <cuda_runtime.h>
#include <cuda_bf16.h>
#include <cuda_fp16.h>
#include <math.h>
#include <stdint.h>

// ---------------- problem constants ----------------
#define BATCH 8
#define NS 512
#define NT 512
#define NSRC 4096
#define NTOT 8192
#define NEDGE 32768
#define EMBED 128
#define ORI 1024
#define CONV_IN 256
#define FINAL_IN 1408
#define KK 25
#define YW 3200
#define CHUNK 32
#define NCHUNK 1024
#define K0PAD 1088
#define KLPAD 192

typedef __nv_bfloat16 bf16;
typedef __half fp16;

template <typename A, typename B> struct same_t { static constexpr bool v = false; };
template <typename A> struct same_t<A, A> { static constexpr bool v = true; };

// ---------------- device scratch ----------------
__device__ __align__(16) bf16 g_xcat_h[NTOT * K0PAD];
__device__ __align__(16) bf16 g_xcat_l[NTOT * K0PAD];
__device__ __align__(16) bf16 g_Xh[BATCH * NS * NT];
__device__ __align__(16) bf16 g_Xl[BATCH * NS * NT];
__device__ __align__(16) bf16 g_XTh[BATCH * NS * NT];
__device__ __align__(16) bf16 g_XTl[BATCH * NS * NT];
__device__ __align__(16) bf16 g_xinT_h[EMBED * NTOT];
__device__ __align__(16) bf16 g_xinT_l[EMBED * NTOT];
__device__ __align__(16) fp16 g_cat_h[NTOT * CONV_IN];
__device__ __align__(16) fp16 g_cat_l[NTOT * CONV_IN];
__device__ __align__(16) bf16 g_feat_h[NTOT * FINAL_IN];
__device__ __align__(16) bf16 g_feat_l[NTOT * FINAL_IN];
__device__ __align__(16) bf16 g_hh[NTOT * EMBED];
__device__ __align__(16) bf16 g_hl[NTOT * EMBED];
__device__ __align__(16) fp16 g_WrT_h[3 * YW * CONV_IN];
__device__ __align__(16) fp16 g_WrT_l[3 * YW * CONV_IN];
__device__ __align__(16) bf16 g_WT0_h[EMBED * K0PAD];
__device__ __align__(16) bf16 g_WT0_l[EMBED * K0PAD];
__device__ __align__(16) bf16 g_WTl_h[2 * EMBED * KLPAD];
__device__ __align__(16) bf16 g_WTl_l[2 * EMBED * KLPAD];
__device__ __align__(16) fp16 g_rtT_h[3 * EMBED * CONV_IN];
__device__ __align__(16) fp16 g_rtT_l[3 * EMBED * CONV_IN];
__device__ __align__(16) bf16 g_fwT_h[EMBED * FINAL_IN];
__device__ __align__(16) bf16 g_fwT_l[EMBED * FINAL_IN];
__device__ float g_xin[NTOT * EMBED];
__device__ float g_msg[NTOT * EMBED];
__device__ float g_rootb[NTOT * EMBED];
__device__ float g_hf[NTOT * EMBED];
__device__ __align__(16) fp16 g_Y[NTOT * YW];     // 52 MB, fp16
__device__ float g_extra[NTOT * 40];
__device__ float g_sum[NTOT];
__device__ int   g_cnt[NCHUNK * 4096];
__device__ int   g_tot[4096];
__device__ int   g_off_s[4097];
__device__ int   g_eid_s[NEDGE];
__device__ int   g_off_t[4097];
__device__ int   g_eid_t[NEDGE];

// ---------------- helpers ----------------
__device__ __forceinline__ void vsplit(float v, bf16& h, bf16& l) {
    h = __float2bfloat16(v);
    l = __float2bfloat16(v - __bfloat162float(h));
}
__device__ __forceinline__ void vsplit(float v, fp16& h, fp16& l) {
    h = __float2half_rn(v);
    l = __float2half_rn(v - __half2float(h));
}
__device__ __forceinline__ uint32_t smem_u32(const void* p) {
    uint32_t a;
    asm("{ .reg .u64 t; cvta.to.shared.u64 t, %1; cvt.u32.u64 %0, t; }" : "=r"(a) : "l"(p));
    return a;
}
__device__ __forceinline__ void cp16(uint32_t s, const void* g) {
    asm volatile("cp.async.cg.shared.global [%0], [%1], 16;" :: "r"(s), "l"(g));
}
__device__ __forceinline__ void ldsm4(uint32_t* r, uint32_t a) {
    asm volatile("ldmatrix.sync.aligned.m8n8.x4.shared.b16 {%0,%1,%2,%3}, [%4];"
                 : "=r"(r[0]), "=r"(r[1]), "=r"(r[2]), "=r"(r[3]) : "r"(a));
}
__device__ __forceinline__ void ldsm2(uint32_t* r, uint32_t a) {
    asm volatile("ldmatrix.sync.aligned.m8n8.x2.shared.b16 {%0,%1}, [%2];"
                 : "=r"(r[0]), "=r"(r[1]) : "r"(a));
}
__device__ __forceinline__ void mma_bf16_(float* d, const uint32_t* a, const uint32_t* b) {
    asm volatile("mma.sync.aligned.m16n8k16.row.col.f32.bf16.bf16.f32 "
                 "{%0,%1,%2,%3}, {%4,%5,%6,%7}, {%8,%9}, {%0,%1,%2,%3};"
                 : "+f"(d[0]), "+f"(d[1]), "+f"(d[2]), "+f"(d[3])
                 : "r"(a[0]), "r"(a[1]), "r"(a[2]), "r"(a[3]), "r"(b[0]), "r"(b[1]));
}
__device__ __forceinline__ void mma_f16_(float* d, const uint32_t* a, const uint32_t* b) {
    asm volatile("mma.sync.aligned.m16n8k16.row.col.f32.f16.f16.f32 "
                 "{%0,%1,%2,%3}, {%4,%5,%6,%7}, {%8,%9}, {%0,%1,%2,%3};"
                 : "+f"(d[0]), "+f"(d[1]), "+f"(d[2]), "+f"(d[3])
                 : "r"(a[0]), "r"(a[1]), "r"(a[2]), "r"(a[3]), "r"(b[0]), "r"(b[1]));
}
template <typename T>
__device__ __forceinline__ void mma_t(float* d, const uint32_t* a, const uint32_t* b) {
    if constexpr (same_t<T, fp16>::v) mma_f16_(d, a, b);
    else                              mma_bf16_(d, a, b);
}

// ======================================================================
// T-typed split GEMM core. PASSES=3: Ah*Bh + Ah*Bl + Al*Bh.
// PASSES=2: Ah*Bh + Ah*Bl (Al never staged).
// A: [m][k] rows, B: [n][k] rows. CTA tile (32*MT) x 128. K mult of 32.
// ======================================================================
template <int MT, typename T, int PASSES, typename OT>
__device__ __forceinline__ void bgemm_core(
    const T* __restrict__ Ah, const T* __restrict__ Al, int lda,
    const T* __restrict__ Bh, const T* __restrict__ Bl, int ldb,
    OT* __restrict__ C, int ldc, const float* __restrict__ bias,
    int K, int m0, int n0, char* smem)
{
    constexpr int ROWSA = 32 * MT;
    constexpr int SEGSA = ROWSA * 4;
    constexpr int A_MATS = (PASSES == 3) ? 2 : 1;
    constexpr int SEGS = A_MATS * SEGSA + 1024;
    constexpr int PER = (SEGS + 255) / 256;
    constexpr int BOFF = A_MATS * ROWSA * 80;
    constexpr int STAGE = BOFF + 20480;
    constexpr bool GUARD = (SEGS % 256) != 0;

    const uint32_t sb = smem_u32(smem);
    const int tid = threadIdx.x, wid = tid >> 5, lane = tid & 31;
    const int wm = wid & 1, wn = wid >> 1;

    // ---- per-thread staging roles, computed once ----
    const T* gp[PER];
    uint32_t sd[PER];
#pragma unroll
    for (int i = 0; i < PER; i++) {
        int idx = tid + i * 256;
        gp[i] = nullptr; sd[i] = 0;
        if (!GUARD || idx < SEGS) {
            if (idx < SEGSA) {
                int r = idx >> 2, sg = idx & 3;
                gp[i] = Ah + (long long)(m0 + r) * lda + sg * 8;
                sd[i] = sb + r * 80 + sg * 16;
            } else if (PASSES == 3 && idx < 2 * SEGSA) {
                int j = idx - SEGSA; int r = j >> 2, sg = j & 3;
                gp[i] = Al + (long long)(m0 + r) * lda + sg * 8;
                sd[i] = sb + ROWSA * 80 + r * 80 + sg * 16;
            } else {
                int j = idx - A_MATS * SEGSA;
                int mat = j >> 9, r = (j >> 2) & 127, sg = j & 3;
                gp[i] = (mat ? Bl : Bh) + (long long)(n0 + r) * ldb + sg * 8;
                sd[i] = sb + BOFF + mat * 10240 + r * 80 + sg * 16;
            }
        }
    }

    const int nch = K >> 5;
    float acc[MT][4][4];
#pragma unroll
    for (int i = 0; i < MT; i++)
#pragma unroll
        for (int j = 0; j < 4; j++)
#pragma unroll
            for (int q = 0; q < 4; q++) acc[i][j][q] = 0.f;

    auto issue = [&](uint32_t bufoff) {
#pragma unroll
        for (int i = 0; i < PER; i++) {
            if (!GUARD || gp[i]) { cp16(sd[i] + bufoff, gp[i]); gp[i] += 32; }
        }
        asm volatile("cp.async.commit_group;");
    };

    issue(0);
    int cur = 0;
    for (int c = 0; c < nch; c++) {
        if (c + 1 < nch) { issue((cur ^ 1) * STAGE); asm volatile("cp.async.wait_group 1;"); }
        else             { asm volatile("cp.async.wait_group 0;"); }
        __syncthreads();

        const uint32_t base   = sb + cur * STAGE;
        const uint32_t alBase = base + ROWSA * 80;
        const uint32_t bhBase = base + BOFF;
        const uint32_t blBase = bhBase + 10240;
        const uint32_t aRow = (uint32_t)(wm * 16 * MT) + (lane & 15);
        const uint32_t aK   = (lane >> 4) * 16;
        const uint32_t bRow = (uint32_t)(wn * 32) + (lane & 7);
        const uint32_t bK   = ((lane >> 3) & 1) * 16;
#pragma unroll
        for (int s = 0; s < 2; s++) {
            uint32_t a[MT][4], b[4][2];
            if (PASSES == 2) {
#pragma unroll
                for (int mt = 0; mt < MT; mt++)
                    ldsm4(a[mt], base + (aRow + mt * 16) * 80 + s * 32 + aK);
#pragma unroll
                for (int nt = 0; nt < 4; nt++)
                    ldsm2(b[nt], bhBase + (bRow + nt * 8) * 80 + s * 32 + bK);
#pragma unroll
                for (int mt = 0; mt < MT; mt++)
#pragma unroll
                    for (int nt = 0; nt < 4; nt++) mma_t<T>(acc[mt][nt], a[mt], b[nt]);
#pragma unroll
                for (int nt = 0; nt < 4; nt++)
                    ldsm2(b[nt], blBase + (bRow + nt * 8) * 80 + s * 32 + bK);
#pragma unroll
                for (int mt = 0; mt < MT; mt++)
#pragma unroll
                    for (int nt = 0; nt < 4; nt++) mma_t<T>(acc[mt][nt], a[mt], b[nt]);
            } else if (MT <= 2) {
                uint32_t al[MT][4];
#pragma unroll
                for (int mt = 0; mt < MT; mt++)
                    ldsm4(a[mt], base + (aRow + mt * 16) * 80 + s * 32 + aK);
#pragma unroll
                for (int mt = 0; mt < MT; mt++)
                    ldsm4(al[mt], alBase + (aRow + mt * 16) * 80 + s * 32 + aK);
#pragma unroll
                for (int nt = 0; nt < 4; nt++)
                    ldsm2(b[nt], bhBase + (bRow + nt * 8) * 80 + s * 32 + bK);
#pragma unroll
                for (int mt = 0; mt < MT; mt++)
#pragma unroll
                    for (int nt = 0; nt < 4; nt++) {
                        mma_t<T>(acc[mt][nt], a[mt], b[nt]);
                        mma_t<T>(acc[mt][nt], al[mt], b[nt]);
                    }
#pragma unroll
                for (int nt = 0; nt < 4; nt++)
                    ldsm2(b[nt], blBase + (bRow + nt * 8) * 80 + s * 32 + bK);
#pragma unroll
                for (int mt = 0; mt < MT; mt++)
#pragma unroll
                    for (int nt = 0; nt < 4; nt++) mma_t<T>(acc[mt][nt], a[mt], b[nt]);
            } else {
#pragma unroll
                for (int mt = 0; mt < MT; mt++)
                    ldsm4(a[mt], base + (aRow + mt * 16) * 80 + s * 32 + aK);
#pragma unroll
                for (int nt = 0; nt < 4; nt++)
                    ldsm2(b[nt], bhBase + (bRow + nt * 8) * 80 + s * 32 + bK);
#pragma unroll
                for (int mt = 0; mt < MT; mt++)
#pragma unroll
                    for (int nt = 0; nt < 4; nt++) mma_t<T>(acc[mt][nt], a[mt], b[nt]);
#pragma unroll
                for (int nt = 0; nt < 4; nt++)
                    ldsm2(b[nt], blBase + (bRow + nt * 8) * 80 + s * 32 + bK);
#pragma unroll
                for (int mt = 0; mt < MT; mt++)
#pragma unroll
                    for (int nt = 0; nt < 4; nt++) mma_t<T>(acc[mt][nt], a[mt], b[nt]);
#pragma unroll
                for (int nt = 0; nt < 4; nt++)
                    ldsm2(b[nt], bhBase + (bRow + nt * 8) * 80 + s * 32 + bK);
#pragma unroll
                for (int mt = 0; mt < MT; mt++)
                    ldsm4(a[mt], alBase + (aRow + mt * 16) * 80 + s * 32 + aK);
#pragma unroll
                for (int mt = 0; mt < MT; mt++)
#pragma unroll
                    for (int nt = 0; nt < 4; nt++) mma_t<T>(acc[mt][nt], a[mt], b[nt]);
            }
        }
        __syncthreads();
        cur ^= 1;
    }

    const int rbase = m0 + wm * 16 * MT + (lane >> 2);
    const int cbase = n0 + wn * 32 + 2 * (lane & 3);
#pragma unroll
    for (int mt = 0; mt < MT; mt++) {
#pragma unroll
        for (int nt = 0; nt < 4; nt++) {
            int r = rbase + mt * 16, cc = cbase + nt * 8;
            float b0 = 0.f, b1 = 0.f;
            if (bias) { b0 = bias[cc]; b1 = bias[cc + 1]; }
            float e00 = acc[mt][nt][0] + b0, e01 = acc[mt][nt][1] + b1;
            float e10 = acc[mt][nt][2] + b0, e11 = acc[mt][nt][3] + b1;
            if constexpr (same_t<OT, fp16>::v) {
                *(__half2*)(C + (long long)r * ldc + cc)       = __floats2half2_rn(e00, e01);
                *(__half2*)(C + (long long)(r + 8) * ldc + cc) = __floats2half2_rn(e10, e11);
            } else {
                *(float2*)(C + (long long)r * ldc + cc)       = make_float2(e00, e01);
                *(float2*)(C + (long long)(r + 8) * ldc + cc) = make_float2(e10, e11);
            }
        }
    }
}

template <int MT, typename T, int PASSES, typename OT>
__global__ void __launch_bounds__(256, 2) bgemm(
    const T* __restrict__ Ah, const T* __restrict__ Al, int lda, long long sA,
    const T* __restrict__ Bh, const T* __restrict__ Bl, int ldb, long long sB,
    OT* __restrict__ C, int ldc, long long sC,
    const float* __restrict__ bias, int K)
{
    extern __shared__ char smem[];
    bgemm_core<MT, T, PASSES, OT>(
        Ah + (long long)blockIdx.z * sA, Al + (long long)blockIdx.z * sA, lda,
        Bh + (long long)blockIdx.z * sB, Bl + (long long)blockIdx.z * sB, ldb,
        C + (long long)blockIdx.z * sC, ldc, bias, K,
        blockIdx.y * 32 * MT, blockIdx.x * 128, smem);
}

// fused msg GEMM: z<8 -> tgt_msg (Xt[b] @ xp_t), z>=8 -> src_msg (Xt[b]^T @ xp_s)
__global__ void __launch_bounds__(256, 2) bgemm_msg(
    const bf16* __restrict__ Xh, const bf16* __restrict__ Xl,
    const bf16* __restrict__ XTh, const bf16* __restrict__ XTl,
    const bf16* __restrict__ xinT_h, const bf16* __restrict__ xinT_l,
    float* __restrict__ msg)
{
    extern __shared__ char smem[];
    const int z = blockIdx.z, b = z & 7, sel = z >> 3;
    const bf16* Ah = (sel ? XTh : Xh) + (long long)b * NS * NT;
    const bf16* Al = (sel ? XTl : Xl) + (long long)b * NS * NT;
    const bf16* Bh = xinT_h + (sel ? 0 : NSRC) + b * 512;
    const bf16* Bl = xinT_l + (sel ? 0 : NSRC) + b * 512;
    float* C = msg + (long long)(sel ? NSRC * EMBED : 0) + (long long)b * 512 * EMBED;
    bgemm_core<1, bf16, 3, float>(Ah, Al, 512, Bh, Bl, NTOT, C, EMBED,
                                  nullptr, 512, blockIdx.y * 32, 0, smem);
}

// ---------------- transpose + split: fp32 [R][C] -> T [C][Rpad] ----------------
template <typename OT>
__global__ void k_convT(const float* __restrict__ in, int R, int C, int ldin, long long sIn,
                        OT* __restrict__ oh, OT* __restrict__ ol, int Rpad, long long sOut) {
    __shared__ float t[32][33];
    in += (long long)blockIdx.z * sIn;
    oh += (long long)blockIdx.z * sOut;
    ol += (long long)blockIdx.z * sOut;
    int r0 = blockIdx.y * 32, c0 = blockIdx.x * 32;
    for (int i = threadIdx.y; i < 32; i += 8) {
        int r = r0 + i, c = c0 + threadIdx.x;
        t[i][threadIdx.x] = (r < R && c < C) ? in[(long long)r * ldin + c] : 0.f;
    }
    __syncthreads();
    for (int i = threadIdx.y; i < 32; i += 8) {
        int c = c0 + i, r = r0 + threadIdx.x;
        if (c < C && r < Rpad) {
            OT h, l; vsplit(t[threadIdx.x][i], h, l);
            oh[(long long)c * Rpad + r] = h;
            ol[(long long)c * Rpad + r] = l;
        }
    }
}
__global__ void k_convS(const float* __restrict__ in, bf16* __restrict__ oh,
                        bf16* __restrict__ ol, int n) {
    int i = (blockIdx.x * 256 + threadIdx.x) * 4;
    if (i >= n) return;
    float4 v = *(const float4*)(in + i);
    __nv_bfloat162 h01 = __floats2bfloat162_rn(v.x, v.y);
    __nv_bfloat162 h23 = __floats2bfloat162_rn(v.z, v.w);
    __nv_bfloat162 l01 = __floats2bfloat162_rn(v.x - __bfloat162float(h01.x),
                                               v.y - __bfloat162float(h01.y));
    __nv_bfloat162 l23 = __floats2bfloat162_rn(v.z - __bfloat162float(h23.x),
                                               v.w - __bfloat162float(h23.y));
    *(__nv_bfloat162*)(oh + i)     = h01;
    *(__nv_bfloat162*)(oh + i + 2) = h23;
    *(__nv_bfloat162*)(ol + i)     = l01;
    *(__nv_bfloat162*)(ol + i + 2) = l23;
}

// ---------------- misc kernels ----------------
__global__ void k_rowsum(const float* __restrict__ Xt, float* __restrict__ rs) {
    int n = blockIdx.x;
    const float* row = Xt + (long long)n * NT;
    __shared__ float sm[256];
    float s = row[threadIdx.x] + row[threadIdx.x + 256];
    sm[threadIdx.x] = s; __syncthreads();
    for (int st = 128; st > 0; st >>= 1) {
        if (threadIdx.x < st) sm[threadIdx.x] += sm[threadIdx.x + st];
        __syncthreads();
    }
    if (threadIdx.x == 0) rs[n] = sm[0];
}
__global__ void k_colsum(const float* __restrict__ Xt, float* __restrict__ cs) {
    int b = blockIdx.x, t = threadIdx.x;
    float s = 0.f;
    const float* base = Xt + (long long)b * NS * NT + t;
    for (int srow = 0; srow < NS; srow++) s += base[srow * NT];
    cs[b * NT + t] = s;
}
__global__ void k_extra(const float* __restrict__ sums, const float* __restrict__ tvec,
                        float* __restrict__ extra) {
    int n = blockIdx.x * blockDim.x + threadIdx.x;
    if (n >= NTOT) return;
    float x = sums[n] * 0.1f;
    float tb = tvec[(n >> 9) & 7];
    const float c = -1.0233711524418064f;
#pragma unroll
    for (int i = 0; i < 10; i++) {
        float f = expf(c * (float)i);
        float ax = x * f, at = tb * f;
        extra[n * 40 + i]      = sinf(ax);
        extra[n * 40 + 10 + i] = cosf(ax);
        extra[n * 40 + 20 + i] = sinf(at);
        extra[n * 40 + 30 + i] = cosf(at);
    }
}
__global__ void k_copyx(const float* __restrict__ xs, const float* __restrict__ xt,
                        bf16* __restrict__ fh, bf16* __restrict__ fl) {
    int n = blockIdx.x;
    const float* x = (n < NSRC) ? xs + (long long)n * ORI : xt + (long long)(n - NSRC) * ORI;
    int c = threadIdx.x * 4;   // 256 threads x 4 = 1024
    float4 v = *(const float4*)(x + c);
    bf16 h0, l0, h1, l1, h2, l2, h3, l3;
    vsplit(v.x, h0, l0); vsplit(v.y, h1, l1);
    vsplit(v.z, h2, l2); vsplit(v.w, h3, l3);
    long long o = (long long)n * FINAL_IN + c;
    fh[o] = h0; fh[o + 1] = h1; fh[o + 2] = h2; fh[o + 3] = h3;
    fl[o] = l0; fl[o + 1] = l1; fl[o + 2] = l2; fl[o + 3] = l3;
}
__global__ void k_xcat0(const float* __restrict__ xs, const float* __restrict__ xt,
                        const float* __restrict__ extra,
                        bf16* __restrict__ oh, bf16* __restrict__ ol) {
    int n = blockIdx.x;
    const float* x = (n < NSRC) ? xs + (long long)n * ORI : xt + (long long)(n - NSRC) * ORI;
    const float* ex = extra + n * 40;
    for (int q = threadIdx.x; q < K0PAD / 4; q += 256) {
        int c = q * 4;
        float4 v;
        if (c < ORI)        v = *(const float4*)(x + c);
        else if (c < 1064)  v = *(const float4*)(ex + (c - ORI));
        else                v = make_float4(0.f, 0.f, 0.f, 0.f);
        __nv_bfloat162 h01 = __floats2bfloat162_rn(v.x, v.y);
        __nv_bfloat162 h23 = __floats2bfloat162_rn(v.z, v.w);
        __nv_bfloat162 l01 = __floats2bfloat162_rn(v.x - __bfloat162float(h01.x),
                                                   v.y - __bfloat162float(h01.y));
        __nv_bfloat162 l23 = __floats2bfloat162_rn(v.z - __bfloat162float(h23.x),
                                                   v.w - __bfloat162float(h23.y));
        long long o = (long long)n * K0PAD + c;
        *(__nv_bfloat162*)(oh + o)     = h01;
        *(__nv_bfloat162*)(oh + o + 2) = h23;
        *(__nv_bfloat162*)(ol + o)     = l01;
        *(__nv_bfloat162*)(ol + o + 2) = l23;
    }
}
__global__ void k_xcatL(const bf16* __restrict__ fh, const bf16* __restrict__ fl,
                        const float* __restrict__ extra,
                        bf16* __restrict__ oh, bf16* __restrict__ ol, int l) {
    int n = blockIdx.x, c = threadIdx.x;   // 192 threads
    bf16 h = __float2bfloat16(0.f), lo = h;
    if (c < 128) {
        long long o = (long long)n * FINAL_IN + ORI + (l - 1) * EMBED + c;
        h = fh[o]; lo = fl[o];
    } else if (c < 168) {
        vsplit(extra[n * 40 + (c - 128)], h, lo);
    }
    oh[(long long)n * KLPAD + c] = h;
    ol[(long long)n * KLPAD + c] = lo;
}
__global__ void k_cat(const float* __restrict__ xin, const float* __restrict__ msg,
                      fp16* __restrict__ oh, fp16* __restrict__ ol) {
    int n = blockIdx.x, d = threadIdx.x;
    float v;
    if (d < EMBED) v = xin[n * EMBED + d];
    else           v = xin[n * EMBED + d - EMBED] - msg[n * EMBED + d - EMBED];
    fp16 h, l; vsplit(v, h, l);
    oh[(long long)n * CONV_IN + d] = h;
    ol[(long long)n * CONV_IN + d] = l;
}

// ----- stable CSR build (cnt layout: [chunk][dst], coalesced) -----
__global__ void k_count(const int* __restrict__ ei, int* __restrict__ cnt) {
    int e = blockIdx.x * 256 + threadIdx.x;
    int d = ei[NEDGE + e];
    atomicAdd(&cnt[(e >> 5) * 4096 + d], 1);
}
__global__ void k_colscan(int* __restrict__ cnt, int* __restrict__ tot) {
    int d = blockIdx.x * 256 + threadIdx.x;
    if (d >= 4096) return;
    int run = 0;
    for (int c = 0; c < NCHUNK; c++) {
        int v = cnt[c * 4096 + d];
        cnt[c * 4096 + d] = run;
        run += v;
    }
    tot[d] = run;
}
__global__ void k_scan(const int* __restrict__ tot, int* __restrict__ off) {
    __shared__ int s[1024];
    int tid = threadIdx.x;
    int v[4]; int sum = 0;
#pragma unroll
    for (int i = 0; i < 4; i++) { v[i] = tot[tid * 4 + i]; sum += v[i]; }
    s[tid] = sum; __syncthreads();
    for (int d = 1; d < 1024; d <<= 1) {
        int x = (tid >= d) ? s[tid - d] : 0;
        __syncthreads();
        s[tid] += x;
        __syncthreads();
    }
    int run = (tid == 0) ? 0 : s[tid - 1];
#pragma unroll
    for (int i = 0; i < 4; i++) { off[tid * 4 + i] = run; run += v[i]; }
    if (tid == 1023) off[4096] = run;
}
__global__ void k_place(const int* __restrict__ ei, const int* __restrict__ off,
                        int* __restrict__ cnt, int* __restrict__ eid) {
    int c = blockIdx.x * 256 + threadIdx.x;
    if (c >= NCHUNK) return;
    for (int j = 0; j < CHUNK; j++) {
        int e = c * CHUNK + j;
        int d = ei[NEDGE + e];
        int r = cnt[c * 4096 + d];
        cnt[c * 4096 + d] = r + 1;
        eid[off[d] + r] = e;
    }
}

// ----- spline gather (Y fp16) + mean + root + tanh -> feat hi/lo -----
__global__ void k_spline_agg(const fp16* __restrict__ Y, const float* __restrict__ rootb,
                             const int* __restrict__ off, const int* __restrict__ eid,
                             const int* __restrict__ ei, const float* __restrict__ ea,
                             bf16* __restrict__ oh, bf16* __restrict__ ol) {
    int n = blockIdx.x, d = threadIdx.x;       // 128
    int beg = off[n], end = off[n + 1];

    auto contrib = [&](int e) -> float {
        int src = ei[e];
        float v0 = ea[e * 2] * 4.f, v1 = ea[e * 2 + 1] * 4.f;
        float l0 = floorf(v0), l1 = floorf(v1);
        float f0 = v0 - l0, f1 = v1 - l1;
        int i0 = (int)l0, i1 = (int)l1;
        const fp16* Ys = Y + (long long)src * YW;
        float r = 0.f;
#pragma unroll
        for (int s1 = 0; s1 < 2; s1++)
#pragma unroll
            for (int s0 = 0; s0 < 2; s0++) {
                int a0 = min(max(i0 + s0, 0), 4);
                int a1 = min(max(i1 + s1, 0), 4);
                float w = (s0 ? f0 : 1.f - f0) * (s1 ? f1 : 1.f - f1);
                r += w * __half2float(Ys[(a0 + 5 * a1) * EMBED + d]);
            }
        return r;
    };

    float acc0 = 0.f, acc1 = 0.f;
    int j = beg;
    for (; j + 2 <= end; j += 2) {
        acc0 += contrib(eid[j]);
        acc1 += contrib(eid[j + 1]);
    }
    if (j < end) acc0 += contrib(eid[j]);
    float acc = acc0 + acc1;

    float deg = (float)(end - beg);
    acc = acc / fmaxf(deg, 1.f);
    float v = tanhf(acc + rootb[n * EMBED + d]);
    bf16 h, l; vsplit(v, h, l);
    oh[(long long)n * FINAL_IN + d] = h;
    ol[(long long)n * FINAL_IN + d] = l;
}

__global__ void k_softmax(float* __restrict__ out) {
    int r = blockIdx.x;
    float* row = out + (long long)r * NT;
    __shared__ float sm[256];
    int tid = threadIdx.x;
    float a = row[tid], b = row[tid + 256];
    sm[tid] = fmaxf(a, b); __syncthreads();
    for (int s = 128; s > 0; s >>= 1) {
        if (tid < s) sm[tid] = fmaxf(sm[tid], sm[tid + s]);
        __syncthreads();
    }
    float mx = sm[0]; __syncthreads();
    float ea = expf(a - mx), eb = expf(b - mx);
    sm[tid] = ea + eb; __syncthreads();
    for (int s = 128; s > 0; s >>= 1) {
        if (tid < s) sm[tid] += sm[tid + s];
        __syncthreads();
    }
    float inv = 1.f / sm[0];
    row[tid] = ea * inv;
    row[tid + 256] = eb * inv;
}

// ---------------- host ----------------
#define STG(MT, AM) (2 * ((AM) * (MT) * 32 * 80 + 20480))
#define GS_B1 STG(1, 2)   // 51200
#define GS_B2 STG(2, 2)   // 61440
#define GS_Y4 STG(4, 1)   // 61440
#define GS_R1 STG(1, 1)   // 46080

static void build_csr(const int* ei, int* off, int* eid, int* cnt, int* tot) {
    cudaMemsetAsync(cnt, 0, NCHUNK * 4096 * sizeof(int));
    k_count<<<NEDGE / 256, 256>>>(ei, cnt);
    k_colscan<<<16, 256>>>(cnt, tot);
    k_scan<<<1, 1024>>>(tot, off);
    k_place<<<4, 256>>>(ei, off, cnt, eid);
}

#define GETSYM(v, s) cudaGetSymbolAddress((void**)&v, s)

extern "C" void kernel_launch(void* const* d_in, const int* in_sizes, int n_in,
                              void* d_out, int out_size) {
    const float* t_in      = (const float*)d_in[0];
    const float* Xt        = (const float*)d_in[1];
    const float* x_s       = (const float*)d_in[2];
    const float* x_t       = (const float*)d_in[3];
    const float* ea_s      = (const float*)d_in[4];
    const float* ea_t      = (const float*)d_in[5];
    const float* lin0_w    = (const float*)d_in[6];
    const float* lin0_b    = (const float*)d_in[7];
    const float* lin_w     = (const float*)d_in[8];
    const float* lin_b     = (const float*)d_in[9];
    const float* conv_w    = (const float*)d_in[10];
    const float* conv_root = (const float*)d_in[11];
    const float* conv_bias = (const float*)d_in[12];
    const float* final_w   = (const float*)d_in[13];
    const float* final_b   = (const float*)d_in[14];
    const int*   ei_s      = (const int*)d_in[15];
    const int*   ei_t      = (const int*)d_in[16];
    float* out = (float*)d_out;

    cudaFuncSetAttribute((const void*)bgemm<1, bf16, 3, float>,
                         cudaFuncAttributeMaxDynamicSharedMemorySize, GS_B1);
    cudaFuncSetAttribute((const void*)bgemm<2, bf16, 3, float>,
                         cudaFuncAttributeMaxDynamicSharedMemorySize, GS_B2);
    cudaFuncSetAttribute((const void*)bgemm<4, fp16, 2, fp16>,
                         cudaFuncAttributeMaxDynamicSharedMemorySize, GS_Y4);
    cudaFuncSetAttribute((const void*)bgemm<1, fp16, 2, float>,
                         cudaFuncAttributeMaxDynamicSharedMemorySize, GS_R1);
    cudaFuncSetAttribute((const void*)bgemm_msg,
                         cudaFuncAttributeMaxDynamicSharedMemorySize, GS_B1);

    bf16 *xcat_h, *xcat_l, *Xh, *Xl, *XTh, *XTl, *xinT_h, *xinT_l;
    fp16 *cat_h, *cat_l, *WrT_h, *WrT_l, *rtT_h, *rtT_l, *Y;
    bf16 *feat_h, *feat_l, *hh, *hl, *WT0_h, *WT0_l, *WTl_h, *WTl_l, *fwT_h, *fwT_l;
    float *xin, *msg, *rootb, *hf, *extra, *sums;
    int *cnt, *tot, *off_s, *eid_s, *off_t, *eid_t;
    GETSYM(xcat_h, g_xcat_h); GETSYM(xcat_l, g_xcat_l);
    GETSYM(Xh, g_Xh); GETSYM(Xl, g_Xl); GETSYM(XTh, g_XTh); GETSYM(XTl, g_XTl);
    GETSYM(xinT_h, g_xinT_h); GETSYM(xinT_l, g_xinT_l);
    GETSYM(cat_h, g_cat_h); GETSYM(cat_l, g_cat_l);
    GETSYM(feat_h, g_feat_h); GETSYM(feat_l, g_feat_l);
    GETSYM(hh, g_hh); GETSYM(hl, g_hl);
    GETSYM(WrT_h, g_WrT_h); GETSYM(WrT_l, g_WrT_l);
    GETSYM(WT0_h, g_WT0_h); GETSYM(WT0_l, g_WT0_l);
    GETSYM(WTl_h, g_WTl_h); GETSYM(WTl_l, g_WTl_l);
    GETSYM(rtT_h, g_rtT_h); GETSYM(rtT_l, g_rtT_l);
    GETSYM(fwT_h, g_fwT_h); GETSYM(fwT_l, g_fwT_l);
    GETSYM(xin, g_xin); GETSYM(msg, g_msg); GETSYM(rootb, g_rootb);
    GETSYM(hf, g_hf); GETSYM(Y, g_Y); GETSYM(extra, g_extra); GETSYM(sums, g_sum);
    GETSYM(cnt, g_cnt); GETSYM(tot, g_tot);
    GETSYM(off_s, g_off_s); GETSYM(eid_s, g_eid_s);
    GETSYM(off_t, g_off_t); GETSYM(eid_t, g_eid_t);

    dim3 tb(32, 8);

    // ---- prep ----
    k_rowsum<<<NSRC, 256>>>(Xt, sums);
    k_colsum<<<BATCH, 512>>>(Xt, sums + NSRC);
    k_extra<<<32, 256>>>(sums, t_in, extra);
    k_xcat0<<<NTOT, 256>>>(x_s, x_t, extra, xcat_h, xcat_l);
    k_convT<bf16><<<dim3(4, K0PAD / 32, 1), tb>>>(lin0_w, 1064, EMBED, EMBED, 0,
                                                  WT0_h, WT0_l, K0PAD, 0);
    bgemm<1, bf16, 3, float><<<dim3(1, NTOT / 32, 1), 256, GS_B1>>>(
        xcat_h, xcat_l, K0PAD, 0, WT0_h, WT0_l, K0PAD, 0,
        xin, EMBED, 0, lin0_b, K0PAD);

    k_convS<<<(BATCH * NS * NT / 4 + 255) / 256, 256>>>(Xt, Xh, Xl, BATCH * NS * NT);
    k_convT<bf16><<<dim3(16, 16, BATCH), tb>>>(Xt, NS, NT, NT, (long long)NS * NT,
                                               XTh, XTl, NS, (long long)NS * NT);
    k_convT<bf16><<<dim3(4, KLPAD / 32, 2), tb>>>(lin_w, 168, EMBED, EMBED, 168 * EMBED,
                                                  WTl_h, WTl_l, KLPAD, (long long)EMBED * KLPAD);
    k_convT<fp16><<<dim3(4, 8, 75), tb>>>(conv_w, CONV_IN, EMBED, EMBED, (long long)CONV_IN * EMBED,
                                          WrT_h, WrT_l, CONV_IN, (long long)EMBED * CONV_IN);
    k_convT<fp16><<<dim3(4, 8, 3), tb>>>(conv_root, CONV_IN, EMBED, EMBED, (long long)CONV_IN * EMBED,
                                         rtT_h, rtT_l, CONV_IN, (long long)EMBED * CONV_IN);
    k_convT<bf16><<<dim3(4, FINAL_IN / 32, 1), tb>>>(final_w, FINAL_IN, EMBED, EMBED, 0,
                                                     fwT_h, fwT_l, FINAL_IN, 0);
    k_copyx<<<NTOT, 256>>>(x_s, x_t, feat_h, feat_l);
    build_csr(ei_s, off_s, eid_s, cnt, tot);
    build_csr(ei_t, off_t, eid_t, cnt, tot);

    for (int l = 0; l < 3; l++) {
        if (l > 0) {
            k_xcatL<<<NTOT, 192>>>(feat_h, feat_l, extra, xcat_h, xcat_l, l);
            const bf16* wh = WTl_h + (long long)(l - 1) * EMBED * KLPAD;
            const bf16* wl = WTl_l + (long long)(l - 1) * EMBED * KLPAD;
            bgemm<1, bf16, 3, float><<<dim3(1, NTOT / 32, 1), 256, GS_B1>>>(
                xcat_h, xcat_l, KLPAD, 0, wh, wl, KLPAD, 0,
                xin, EMBED, 0, lin_b + (l - 1) * EMBED, KLPAD);
        }
        // xinT (fp32 -> transposed split)
        k_convT<bf16><<<dim3(4, 256, 1), tb>>>(xin, NTOT, EMBED, EMBED, 0,
                                               xinT_h, xinT_l, NTOT, 0);
        // fused tgt_msg + src_msg
        bgemm_msg<<<dim3(1, 16, 16), 256, GS_B1>>>(Xh, Xl, XTh, XTl, xinT_h, xinT_l, msg);

        k_cat<<<NTOT, 256>>>(xin, msg, cat_h, cat_l);

        // Y = cat @ Wr[l]  (fp16 2-pass, fp16 out)
        bgemm<4, fp16, 2, fp16><<<dim3(YW / 128, NTOT / 128, 1), 256, GS_Y4>>>(
            cat_h, cat_l, CONV_IN, 0,
            WrT_h + (long long)l * YW * CONV_IN, WrT_l + (long long)l * YW * CONV_IN, CONV_IN, 0,
            Y, YW, 0, nullptr, CONV_IN);
        // rootb = cat @ root + bias (fp16 2-pass, fp32 out)
        bgemm<1, fp16, 2, float><<<dim3(1, NTOT / 32, 1), 256, GS_R1>>>(
            cat_h, cat_l, CONV_IN, 0,
            rtT_h + (long long)l * EMBED * CONV_IN, rtT_l + (long long)l * EMBED * CONV_IN, CONV_IN, 0,
            rootb, EMBED, 0, conv_bias + l * EMBED, CONV_IN);

        k_spline_agg<<<NSRC, 128>>>(Y, rootb, off_s, eid_s, ei_s, ea_s,
                                    feat_h + ORI + l * EMBED, feat_l + ORI + l * EMBED);
        k_spline_agg<<<NSRC, 128>>>(Y + (long long)NSRC * YW, rootb + (long long)NSRC * EMBED,
                                    off_t, eid_t, ei_t, ea_t,
                                    feat_h + (long long)NSRC * FINAL_IN + ORI + l * EMBED,
                                    feat_l + (long long)NSRC * FINAL_IN + ORI + l * EMBED);
    }

    // h = feat @ final_w + final_b
    bgemm<1, bf16, 3, float><<<dim3(1, NTOT / 32, 1), 256, GS_B1>>>(
        feat_h, feat_l, FINAL_IN, 0, fwT_h, fwT_l, FINAL_IN, 0,
        hf, EMBED, 0, final_b, FINAL_IN);
    k_convS<<<(NTOT * EMBED / 4 + 255) / 256, 256>>>(hf, hh, hl, NTOT * EMBED);

    // sim = h_s @ h_t^T per batch
    bgemm<2, bf16, 3, float><<<dim3(4, 8, 8), 256, GS_B2>>>(
        hh, hl, EMBED, (long long)NS * EMBED,
        hh + (long long)NSRC * EMBED, hl + (long long)NSRC * EMBED, EMBED, (long long)NT * EMBED,
        out, NT, (long long)NS * NT, nullptr, EMBED);

    k_softmax<<<NSRC, 256>>>(out);
}

// round 8
// speedup vs baseline: 1.3385x; 1.3385x over previous
#include <cuda_runtime.h>
#include <cuda_bf16.h>
#include <math.h>
#include <stdint.h>

// ---------------- problem constants ----------------
#define BATCH 8
#define NS 512
#define NT 512
#define NSRC 4096
#define NTOT 8192
#define NEDGE 32768
#define EMBED 128
#define ORI 1024
#define CONV_IN 256
#define FINAL_IN 1408
#define KK 25
#define YW 3200
#define CHUNK 32
#define NCHUNK 1024
#define K0PAD 1088
#define KLPAD 192

typedef __nv_bfloat16 bf16;

// ---------------- device scratch ----------------
__device__ __align__(16) bf16 g_xcat_h[NTOT * K0PAD];
__device__ __align__(16) bf16 g_xcat_l[NTOT * K0PAD];
__device__ __align__(16) bf16 g_Xh[BATCH * NS * NT];
__device__ __align__(16) bf16 g_Xl[BATCH * NS * NT];
__device__ __align__(16) bf16 g_XTh[BATCH * NS * NT];
__device__ __align__(16) bf16 g_XTl[BATCH * NS * NT];
__device__ __align__(16) bf16 g_xinT_h[EMBED * NTOT];
__device__ __align__(16) bf16 g_xinT_l[EMBED * NTOT];
__device__ __align__(16) bf16 g_cat_h[NTOT * CONV_IN];
__device__ __align__(16) bf16 g_cat_l[NTOT * CONV_IN];
__device__ __align__(16) bf16 g_feat_h[NTOT * FINAL_IN];
__device__ __align__(16) bf16 g_feat_l[NTOT * FINAL_IN];
__device__ __align__(16) bf16 g_hh[NTOT * EMBED];
__device__ __align__(16) bf16 g_hl[NTOT * EMBED];
__device__ __align__(16) bf16 g_WrT_h[3 * YW * CONV_IN];
__device__ __align__(16) bf16 g_WrT_l[3 * YW * CONV_IN];
__device__ __align__(16) bf16 g_WT0_h[EMBED * K0PAD];
__device__ __align__(16) bf16 g_WT0_l[EMBED * K0PAD];
__device__ __align__(16) bf16 g_WTl_h[2 * EMBED * KLPAD];
__device__ __align__(16) bf16 g_WTl_l[2 * EMBED * KLPAD];
__device__ __align__(16) bf16 g_rtT_h[3 * EMBED * CONV_IN];
__device__ __align__(16) bf16 g_rtT_l[3 * EMBED * CONV_IN];
__device__ __align__(16) bf16 g_fwT_h[EMBED * FINAL_IN];
__device__ __align__(16) bf16 g_fwT_l[EMBED * FINAL_IN];
__device__ float g_xin[NTOT * EMBED];
__device__ float g_msg[NTOT * EMBED];
__device__ float g_rootb[NTOT * EMBED];
__device__ float g_hf[NTOT * EMBED];
__device__ float g_Y[NTOT * YW];
__device__ float g_extra[NTOT * 40];
__device__ float g_sum[NTOT];
__device__ int   g_cnt[NCHUNK * 4096];
__device__ int   g_tot[4096];
__device__ int   g_off_s[4097];
__device__ int   g_eid_s[NEDGE];
__device__ int   g_off_t[4097];
__device__ int   g_eid_t[NEDGE];

// ---------------- helpers ----------------
__device__ __forceinline__ void vsplit(float v, bf16& h, bf16& l) {
    h = __float2bfloat16(v);
    l = __float2bfloat16(v - __bfloat162float(h));
}
__device__ __forceinline__ uint32_t smem_u32(const void* p) {
    uint32_t a;
    asm("{ .reg .u64 t; cvta.to.shared.u64 t, %1; cvt.u32.u64 %0, t; }" : "=r"(a) : "l"(p));
    return a;
}
__device__ __forceinline__ void cp16(uint32_t s, const void* g) {
    asm volatile("cp.async.cg.shared.global [%0], [%1], 16;" :: "r"(s), "l"(g));
}
__device__ __forceinline__ void ldsm4(uint32_t* r, uint32_t a) {
    asm volatile("ldmatrix.sync.aligned.m8n8.x4.shared.b16 {%0,%1,%2,%3}, [%4];"
                 : "=r"(r[0]), "=r"(r[1]), "=r"(r[2]), "=r"(r[3]) : "r"(a));
}
__device__ __forceinline__ void mma16816(float* d, const uint32_t* a, const uint32_t* b) {
    asm volatile("mma.sync.aligned.m16n8k16.row.col.f32.bf16.bf16.f32 "
                 "{%0,%1,%2,%3}, {%4,%5,%6,%7}, {%8,%9}, {%0,%1,%2,%3};"
                 : "+f"(d[0]), "+f"(d[1]), "+f"(d[2]), "+f"(d[3])
                 : "r"(a[0]), "r"(a[1]), "r"(a[2]), "r"(a[3]), "r"(b[0]), "r"(b[1]));
}

// ======================================================================
// bf16 3-term GEMM core: C = Ah*Bh + Ah*Bl + Al*Bh (+bias), fp32 accum.
// A: [m][k] rows, B: [n][k] rows. CTA tile (32*MT) x 128. K mult of 32.
// B fragments held in registers across all 3 passes (no redundant reload);
// B loaded via ldsm4 (2 n-tiles per instruction).
// ======================================================================
template <int MT>
__device__ __forceinline__ void bgemm_core(
    const bf16* __restrict__ Ah, const bf16* __restrict__ Al, int lda,
    const bf16* __restrict__ Bh, const bf16* __restrict__ Bl, int ldb,
    float* __restrict__ C, int ldc, const float* __restrict__ bias,
    int K, int m0, int n0, char* smem)
{
    constexpr int ROWSA = 32 * MT;
    constexpr int SEGSA = ROWSA * 4;
    constexpr int SEGS  = 2 * SEGSA + 1024;
    constexpr int PER   = (SEGS + 255) / 256;
    constexpr int BOFF  = 2 * ROWSA * 80;
    constexpr int STAGE = BOFF + 20480;
    constexpr bool GUARD = (SEGS % 256) != 0;

    const uint32_t sb = smem_u32(smem);
    const int tid = threadIdx.x, wid = tid >> 5, lane = tid & 31;
    const int wm = wid & 1, wn = wid >> 1;

    // per-thread staging roles, computed once
    const bf16* gp[PER];
    uint32_t sd[PER];
#pragma unroll
    for (int i = 0; i < PER; i++) {
        int idx = tid + i * 256;
        gp[i] = nullptr; sd[i] = 0;
        if (!GUARD || idx < SEGS) {
            if (idx < SEGSA) {
                int r = idx >> 2, sg = idx & 3;
                gp[i] = Ah + (long long)(m0 + r) * lda + sg * 8;
                sd[i] = sb + r * 80 + sg * 16;
            } else if (idx < 2 * SEGSA) {
                int j = idx - SEGSA; int r = j >> 2, sg = j & 3;
                gp[i] = Al + (long long)(m0 + r) * lda + sg * 8;
                sd[i] = sb + ROWSA * 80 + r * 80 + sg * 16;
            } else {
                int j = idx - 2 * SEGSA;
                int mat = j >> 9, r = (j >> 2) & 127, sg = j & 3;
                gp[i] = (mat ? Bl : Bh) + (long long)(n0 + r) * ldb + sg * 8;
                sd[i] = sb + BOFF + mat * 10240 + r * 80 + sg * 16;
            }
        }
    }

    const int nch = K >> 5;
    float acc[MT][4][4];
#pragma unroll
    for (int i = 0; i < MT; i++)
#pragma unroll
        for (int j = 0; j < 4; j++)
#pragma unroll
            for (int q = 0; q < 4; q++) acc[i][j][q] = 0.f;

    auto issue = [&](uint32_t bufoff) {
#pragma unroll
        for (int i = 0; i < PER; i++) {
            if (!GUARD || gp[i]) { cp16(sd[i] + bufoff, gp[i]); gp[i] += 32; }
        }
        asm volatile("cp.async.commit_group;");
    };

    issue(0);
    int cur = 0;
    for (int c = 0; c < nch; c++) {
        if (c + 1 < nch) { issue((cur ^ 1) * STAGE); asm volatile("cp.async.wait_group 1;"); }
        else             { asm volatile("cp.async.wait_group 0;"); }
        __syncthreads();

        const uint32_t base   = sb + cur * STAGE;
        const uint32_t alBase = base + ROWSA * 80;
        const uint32_t bhBase = base + BOFF;
        const uint32_t blBase = bhBase + 10240;
        const uint32_t aRow  = (uint32_t)(wm * 16 * MT) + (lane & 15);
        const uint32_t aK    = (lane >> 4) * 16;
        // ldsm4 B addressing: groups of 8 lanes -> (nt even/odd, k-half)
        const uint32_t bRow4 = (uint32_t)(wn * 32) + ((lane >> 4) & 1) * 8 + (lane & 7);
        const uint32_t bK4   = ((lane >> 3) & 1) * 16;
#pragma unroll
        for (int s = 0; s < 2; s++) {
            uint32_t bh[4][2], bl[4][2], a[4];
            ldsm4(&bh[0][0], bhBase + bRow4 * 80 + s * 32 + bK4);
            ldsm4(&bh[2][0], bhBase + (bRow4 + 16) * 80 + s * 32 + bK4);
            ldsm4(&bl[0][0], blBase + bRow4 * 80 + s * 32 + bK4);
            ldsm4(&bl[2][0], blBase + (bRow4 + 16) * 80 + s * 32 + bK4);
#pragma unroll
            for (int mt = 0; mt < MT; mt++) {
                ldsm4(a, base + (aRow + mt * 16) * 80 + s * 32 + aK);
#pragma unroll
                for (int nt = 0; nt < 4; nt++) mma16816(acc[mt][nt], a, bh[nt]);
#pragma unroll
                for (int nt = 0; nt < 4; nt++) mma16816(acc[mt][nt], a, bl[nt]);
                ldsm4(a, alBase + (aRow + mt * 16) * 80 + s * 32 + aK);
#pragma unroll
                for (int nt = 0; nt < 4; nt++) mma16816(acc[mt][nt], a, bh[nt]);
            }
        }
        __syncthreads();
        cur ^= 1;
    }

    const int rbase = m0 + wm * 16 * MT + (lane >> 2);
    const int cbase = n0 + wn * 32 + 2 * (lane & 3);
#pragma unroll
    for (int mt = 0; mt < MT; mt++) {
#pragma unroll
        for (int nt = 0; nt < 4; nt++) {
            int r = rbase + mt * 16, cc = cbase + nt * 8;
            float b0 = 0.f, b1 = 0.f;
            if (bias) { b0 = bias[cc]; b1 = bias[cc + 1]; }
            float2 v0 = make_float2(acc[mt][nt][0] + b0, acc[mt][nt][1] + b1);
            float2 v1 = make_float2(acc[mt][nt][2] + b0, acc[mt][nt][3] + b1);
            *(float2*)(C + (long long)r * ldc + cc) = v0;
            *(float2*)(C + (long long)(r + 8) * ldc + cc) = v1;
        }
    }
}

template <int MT>
__global__ void __launch_bounds__(256, 2) bgemm(
    const bf16* __restrict__ Ah, const bf16* __restrict__ Al, int lda, long long sA,
    const bf16* __restrict__ Bh, const bf16* __restrict__ Bl, int ldb, long long sB,
    float* __restrict__ C, int ldc, long long sC,
    const float* __restrict__ bias, int K)
{
    extern __shared__ char smem[];
    bgemm_core<MT>(
        Ah + (long long)blockIdx.z * sA, Al + (long long)blockIdx.z * sA, lda,
        Bh + (long long)blockIdx.z * sB, Bl + (long long)blockIdx.z * sB, ldb,
        C + (long long)blockIdx.z * sC, ldc, bias, K,
        blockIdx.y * 32 * MT, blockIdx.x * 128, smem);
}

// fused msg GEMM: z<8 -> tgt_msg (Xt[b] @ xp_t), z>=8 -> src_msg (Xt[b]^T @ xp_s)
__global__ void __launch_bounds__(256, 2) bgemm_msg(
    const bf16* __restrict__ Xh, const bf16* __restrict__ Xl,
    const bf16* __restrict__ XTh, const bf16* __restrict__ XTl,
    const bf16* __restrict__ xinT_h, const bf16* __restrict__ xinT_l,
    float* __restrict__ msg)
{
    extern __shared__ char smem[];
    const int z = blockIdx.z, b = z & 7, sel = z >> 3;
    const bf16* Ah = (sel ? XTh : Xh) + (long long)b * NS * NT;
    const bf16* Al = (sel ? XTl : Xl) + (long long)b * NS * NT;
    const bf16* Bh = xinT_h + (sel ? 0 : NSRC) + b * 512;
    const bf16* Bl = xinT_l + (sel ? 0 : NSRC) + b * 512;
    float* C = msg + (long long)(sel ? NSRC * EMBED : 0) + (long long)b * 512 * EMBED;
    bgemm_core<1>(Ah, Al, 512, Bh, Bl, NTOT, C, EMBED,
                  nullptr, 512, blockIdx.y * 32, 0, smem);
}

// ---------------- transpose + split: fp32 [R][C] -> bf16 [C][Rpad] ----------------
__global__ void k_convT(const float* __restrict__ in, int R, int C, int ldin, long long sIn,
                        bf16* __restrict__ oh, bf16* __restrict__ ol, int Rpad, long long sOut) {
    __shared__ float t[32][33];
    in += (long long)blockIdx.z * sIn;
    oh += (long long)blockIdx.z * sOut;
    ol += (long long)blockIdx.z * sOut;
    int r0 = blockIdx.y * 32, c0 = blockIdx.x * 32;
    for (int i = threadIdx.y; i < 32; i += 8) {
        int r = r0 + i, c = c0 + threadIdx.x;
        t[i][threadIdx.x] = (r < R && c < C) ? in[(long long)r * ldin + c] : 0.f;
    }
    __syncthreads();
    for (int i = threadIdx.y; i < 32; i += 8) {
        int c = c0 + i, r = r0 + threadIdx.x;
        if (c < C && r < Rpad) {
            bf16 h, l; vsplit(t[threadIdx.x][i], h, l);
            oh[(long long)c * Rpad + r] = h;
            ol[(long long)c * Rpad + r] = l;
        }
    }
}
__global__ void k_convS(const float* __restrict__ in, bf16* __restrict__ oh,
                        bf16* __restrict__ ol, int n) {
    int i = (blockIdx.x * 256 + threadIdx.x) * 4;
    if (i >= n) return;
    float4 v = *(const float4*)(in + i);
    __nv_bfloat162 h01 = __floats2bfloat162_rn(v.x, v.y);
    __nv_bfloat162 h23 = __floats2bfloat162_rn(v.z, v.w);
    __nv_bfloat162 l01 = __floats2bfloat162_rn(v.x - __bfloat162float(h01.x),
                                               v.y - __bfloat162float(h01.y));
    __nv_bfloat162 l23 = __floats2bfloat162_rn(v.z - __bfloat162float(h23.x),
                                               v.w - __bfloat162float(h23.y));
    *(__nv_bfloat162*)(oh + i)     = h01;
    *(__nv_bfloat162*)(oh + i + 2) = h23;
    *(__nv_bfloat162*)(ol + i)     = l01;
    *(__nv_bfloat162*)(ol + i + 2) = l23;
}

// ---------------- misc kernels ----------------
__global__ void k_rowsum(const float* __restrict__ Xt, float* __restrict__ rs) {
    int n = blockIdx.x;
    const float* row = Xt + (long long)n * NT;
    __shared__ float sm[256];
    float s = row[threadIdx.x] + row[threadIdx.x + 256];
    sm[threadIdx.x] = s; __syncthreads();
    for (int st = 128; st > 0; st >>= 1) {
        if (threadIdx.x < st) sm[threadIdx.x] += sm[threadIdx.x + st];
        __syncthreads();
    }
    if (threadIdx.x == 0) rs[n] = sm[0];
}
__global__ void k_colsum(const float* __restrict__ Xt, float* __restrict__ cs) {
    int b = blockIdx.x, t = threadIdx.x;
    float s = 0.f;
    const float* base = Xt + (long long)b * NS * NT + t;
    for (int srow = 0; srow < NS; srow++) s += base[srow * NT];
    cs[b * NT + t] = s;
}
__global__ void k_extra(const float* __restrict__ sums, const float* __restrict__ tvec,
                        float* __restrict__ extra) {
    int n = blockIdx.x * blockDim.x + threadIdx.x;
    if (n >= NTOT) return;
    float x = sums[n] * 0.1f;
    float tb = tvec[(n >> 9) & 7];
    const float c = -1.0233711524418064f;
#pragma unroll
    for (int i = 0; i < 10; i++) {
        float f = expf(c * (float)i);
        float ax = x * f, at = tb * f;
        extra[n * 40 + i]      = sinf(ax);
        extra[n * 40 + 10 + i] = cosf(ax);
        extra[n * 40 + 20 + i] = sinf(at);
        extra[n * 40 + 30 + i] = cosf(at);
    }
}
__global__ void k_copyx(const float* __restrict__ xs, const float* __restrict__ xt,
                        bf16* __restrict__ fh, bf16* __restrict__ fl) {
    int n = blockIdx.x;
    const float* x = (n < NSRC) ? xs + (long long)n * ORI : xt + (long long)(n - NSRC) * ORI;
    int c = threadIdx.x * 4;   // 256 threads x 4 = 1024
    float4 v = *(const float4*)(x + c);
    bf16 h0, l0, h1, l1, h2, l2, h3, l3;
    vsplit(v.x, h0, l0); vsplit(v.y, h1, l1);
    vsplit(v.z, h2, l2); vsplit(v.w, h3, l3);
    long long o = (long long)n * FINAL_IN + c;
    fh[o] = h0; fh[o + 1] = h1; fh[o + 2] = h2; fh[o + 3] = h3;
    fl[o] = l0; fl[o + 1] = l1; fl[o + 2] = l2; fl[o + 3] = l3;
}
__global__ void k_xcat0(const float* __restrict__ xs, const float* __restrict__ xt,
                        const float* __restrict__ extra,
                        bf16* __restrict__ oh, bf16* __restrict__ ol) {
    int n = blockIdx.x;
    const float* x = (n < NSRC) ? xs + (long long)n * ORI : xt + (long long)(n - NSRC) * ORI;
    const float* ex = extra + n * 40;
    for (int q = threadIdx.x; q < K0PAD / 4; q += 256) {
        int c = q * 4;
        float4 v;
        if (c < ORI)        v = *(const float4*)(x + c);
        else if (c < 1064)  v = *(const float4*)(ex + (c - ORI));
        else                v = make_float4(0.f, 0.f, 0.f, 0.f);
        __nv_bfloat162 h01 = __floats2bfloat162_rn(v.x, v.y);
        __nv_bfloat162 h23 = __floats2bfloat162_rn(v.z, v.w);
        __nv_bfloat162 l01 = __floats2bfloat162_rn(v.x - __bfloat162float(h01.x),
                                                   v.y - __bfloat162float(h01.y));
        __nv_bfloat162 l23 = __floats2bfloat162_rn(v.z - __bfloat162float(h23.x),
                                                   v.w - __bfloat162float(h23.y));
        long long o = (long long)n * K0PAD + c;
        *(__nv_bfloat162*)(oh + o)     = h01;
        *(__nv_bfloat162*)(oh + o + 2) = h23;
        *(__nv_bfloat162*)(ol + o)     = l01;
        *(__nv_bfloat162*)(ol + o + 2) = l23;
    }
}
__global__ void k_xcatL(const bf16* __restrict__ fh, const bf16* __restrict__ fl,
                        const float* __restrict__ extra,
                        bf16* __restrict__ oh, bf16* __restrict__ ol, int l) {
    int n = blockIdx.x, c = threadIdx.x;   // 192 threads
    bf16 h = __float2bfloat16(0.f), lo = h;
    if (c < 128) {
        long long o = (long long)n * FINAL_IN + ORI + (l - 1) * EMBED + c;
        h = fh[o]; lo = fl[o];
    } else if (c < 168) {
        vsplit(extra[n * 40 + (c - 128)], h, lo);
    }
    oh[(long long)n * KLPAD + c] = h;
    ol[(long long)n * KLPAD + c] = lo;
}
__global__ void k_cat(const float* __restrict__ xin, const float* __restrict__ msg,
                      bf16* __restrict__ oh, bf16* __restrict__ ol) {
    int n = blockIdx.x, d = threadIdx.x;
    float v;
    if (d < EMBED) v = xin[n * EMBED + d];
    else           v = xin[n * EMBED + d - EMBED] - msg[n * EMBED + d - EMBED];
    bf16 h, l; vsplit(v, h, l);
    oh[(long long)n * CONV_IN + d] = h;
    ol[(long long)n * CONV_IN + d] = l;
}

// ----- stable CSR build (cnt layout: [chunk][dst], coalesced) -----
__global__ void k_count(const int* __restrict__ ei, int* __restrict__ cnt) {
    int e = blockIdx.x * 256 + threadIdx.x;
    int d = ei[NEDGE + e];
    atomicAdd(&cnt[(e >> 5) * 4096 + d], 1);
}
__global__ void k_colscan(int* __restrict__ cnt, int* __restrict__ tot) {
    int d = blockIdx.x * 256 + threadIdx.x;
    if (d >= 4096) return;
    int run = 0;
    for (int c = 0; c < NCHUNK; c++) {
        int v = cnt[c * 4096 + d];
        cnt[c * 4096 + d] = run;
        run += v;
    }
    tot[d] = run;
}
__global__ void k_scan(const int* __restrict__ tot, int* __restrict__ off) {
    __shared__ int s[1024];
    int tid = threadIdx.x;
    int v[4]; int sum = 0;
#pragma unroll
    for (int i = 0; i < 4; i++) { v[i] = tot[tid * 4 + i]; sum += v[i]; }
    s[tid] = sum; __syncthreads();
    for (int d = 1; d < 1024; d <<= 1) {
        int x = (tid >= d) ? s[tid - d] : 0;
        __syncthreads();
        s[tid] += x;
        __syncthreads();
    }
    int run = (tid == 0) ? 0 : s[tid - 1];
#pragma unroll
    for (int i = 0; i < 4; i++) { off[tid * 4 + i] = run; run += v[i]; }
    if (tid == 1023) off[4096] = run;
}
__global__ void k_place(const int* __restrict__ ei, const int* __restrict__ off,
                        int* __restrict__ cnt, int* __restrict__ eid) {
    int c = blockIdx.x * 256 + threadIdx.x;
    if (c >= NCHUNK) return;
    for (int j = 0; j < CHUNK; j++) {
        int e = c * CHUNK + j;
        int d = ei[NEDGE + e];
        int r = cnt[c * 4096 + d];
        cnt[c * 4096 + d] = r + 1;
        eid[off[d] + r] = e;
    }
}

// ----- spline gather + mean + root + tanh -> feat hi/lo -----
__global__ void k_spline_agg(const float* __restrict__ Y, const float* __restrict__ rootb,
                             const int* __restrict__ off, const int* __restrict__ eid,
                             const int* __restrict__ ei, const float* __restrict__ ea,
                             bf16* __restrict__ oh, bf16* __restrict__ ol) {
    int n = blockIdx.x, d = threadIdx.x;       // 128
    int beg = off[n], end = off[n + 1];

    auto contrib = [&](int e) -> float {
        int src = ei[e];
        float v0 = ea[e * 2] * 4.f, v1 = ea[e * 2 + 1] * 4.f;
        float l0 = floorf(v0), l1 = floorf(v1);
        float f0 = v0 - l0, f1 = v1 - l1;
        int i0 = (int)l0, i1 = (int)l1;
        const float* Ys = Y + (long long)src * YW;
        float r = 0.f;
#pragma unroll
        for (int s1 = 0; s1 < 2; s1++)
#pragma unroll
            for (int s0 = 0; s0 < 2; s0++) {
                int a0 = min(max(i0 + s0, 0), 4);
                int a1 = min(max(i1 + s1, 0), 4);
                float w = (s0 ? f0 : 1.f - f0) * (s1 ? f1 : 1.f - f1);
                r += w * Ys[(a0 + 5 * a1) * EMBED + d];
            }
        return r;
    };

    float acc0 = 0.f, acc1 = 0.f;
    int j = beg;
    for (; j + 2 <= end; j += 2) {
        acc0 += contrib(eid[j]);
        acc1 += contrib(eid[j + 1]);
    }
    if (j < end) acc0 += contrib(eid[j]);
    float acc = acc0 + acc1;

    float deg = (float)(end - beg);
    acc = acc / fmaxf(deg, 1.f);
    float v = tanhf(acc + rootb[n * EMBED + d]);
    bf16 h, l; vsplit(v, h, l);
    oh[(long long)n * FINAL_IN + d] = h;
    ol[(long long)n * FINAL_IN + d] = l;
}

__global__ void k_softmax(float* __restrict__ out) {
    int r = blockIdx.x;
    float* row = out + (long long)r * NT;
    __shared__ float sm[256];
    int tid = threadIdx.x;
    float a = row[tid], b = row[tid + 256];
    sm[tid] = fmaxf(a, b); __syncthreads();
    for (int s = 128; s > 0; s >>= 1) {
        if (tid < s) sm[tid] = fmaxf(sm[tid], sm[tid + s]);
        __syncthreads();
    }
    float mx = sm[0]; __syncthreads();
    float ea = expf(a - mx), eb = expf(b - mx);
    sm[tid] = ea + eb; __syncthreads();
    for (int s = 128; s > 0; s >>= 1) {
        if (tid < s) sm[tid] += sm[tid + s];
        __syncthreads();
    }
    float inv = 1.f / sm[0];
    row[tid] = ea * inv;
    row[tid + 256] = eb * inv;
}

// ---------------- host ----------------
#define STG(MT) (2 * (2 * (MT) * 32 * 80 + 20480))
#define GS_M1 STG(1)   // 51200
#define GS_M2 STG(2)   // 61440
#define GS_M4 STG(4)   // 81920

static void build_csr(const int* ei, int* off, int* eid, int* cnt, int* tot) {
    cudaMemsetAsync(cnt, 0, NCHUNK * 4096 * sizeof(int));
    k_count<<<NEDGE / 256, 256>>>(ei, cnt);
    k_colscan<<<16, 256>>>(cnt, tot);
    k_scan<<<1, 1024>>>(tot, off);
    k_place<<<4, 256>>>(ei, off, cnt, eid);
}

#define GETSYM(v, s) cudaGetSymbolAddress((void**)&v, s)

extern "C" void kernel_launch(void* const* d_in, const int* in_sizes, int n_in,
                              void* d_out, int out_size) {
    const float* t_in      = (const float*)d_in[0];
    const float* Xt        = (const float*)d_in[1];
    const float* x_s       = (const float*)d_in[2];
    const float* x_t       = (const float*)d_in[3];
    const float* ea_s      = (const float*)d_in[4];
    const float* ea_t      = (const float*)d_in[5];
    const float* lin0_w    = (const float*)d_in[6];
    const float* lin0_b    = (const float*)d_in[7];
    const float* lin_w     = (const float*)d_in[8];
    const float* lin_b     = (const float*)d_in[9];
    const float* conv_w    = (const float*)d_in[10];
    const float* conv_root = (const float*)d_in[11];
    const float* conv_bias = (const float*)d_in[12];
    const float* final_w   = (const float*)d_in[13];
    const float* final_b   = (const float*)d_in[14];
    const int*   ei_s      = (const int*)d_in[15];
    const int*   ei_t      = (const int*)d_in[16];
    float* out = (float*)d_out;

    cudaFuncSetAttribute(bgemm<1>, cudaFuncAttributeMaxDynamicSharedMemorySize, GS_M1);
    cudaFuncSetAttribute(bgemm<2>, cudaFuncAttributeMaxDynamicSharedMemorySize, GS_M2);
    cudaFuncSetAttribute(bgemm<4>, cudaFuncAttributeMaxDynamicSharedMemorySize, GS_M4);
    cudaFuncSetAttribute(bgemm_msg, cudaFuncAttributeMaxDynamicSharedMemorySize, GS_M1);

    bf16 *xcat_h, *xcat_l, *Xh, *Xl, *XTh, *XTl, *xinT_h, *xinT_l, *cat_h, *cat_l;
    bf16 *feat_h, *feat_l, *hh, *hl, *WrT_h, *WrT_l, *WT0_h, *WT0_l, *WTl_h, *WTl_l;
    bf16 *rtT_h, *rtT_l, *fwT_h, *fwT_l;
    float *xin, *msg, *rootb, *hf, *Y, *extra, *sums;
    int *cnt, *tot, *off_s, *eid_s, *off_t, *eid_t;
    GETSYM(xcat_h, g_xcat_h); GETSYM(xcat_l, g_xcat_l);
    GETSYM(Xh, g_Xh); GETSYM(Xl, g_Xl); GETSYM(XTh, g_XTh); GETSYM(XTl, g_XTl);
    GETSYM(xinT_h, g_xinT_h); GETSYM(xinT_l, g_xinT_l);
    GETSYM(cat_h, g_cat_h); GETSYM(cat_l, g_cat_l);
    GETSYM(feat_h, g_feat_h); GETSYM(feat_l, g_feat_l);
    GETSYM(hh, g_hh); GETSYM(hl, g_hl);
    GETSYM(WrT_h, g_WrT_h); GETSYM(WrT_l, g_WrT_l);
    GETSYM(WT0_h, g_WT0_h); GETSYM(WT0_l, g_WT0_l);
    GETSYM(WTl_h, g_WTl_h); GETSYM(WTl_l, g_WTl_l);
    GETSYM(rtT_h, g_rtT_h); GETSYM(rtT_l, g_rtT_l);
    GETSYM(fwT_h, g_fwT_h); GETSYM(fwT_l, g_fwT_l);
    GETSYM(xin, g_xin); GETSYM(msg, g_msg); GETSYM(rootb, g_rootb);
    GETSYM(hf, g_hf); GETSYM(Y, g_Y); GETSYM(extra, g_extra); GETSYM(sums, g_sum);
    GETSYM(cnt, g_cnt); GETSYM(tot, g_tot);
    GETSYM(off_s, g_off_s); GETSYM(eid_s, g_eid_s);
    GETSYM(off_t, g_off_t); GETSYM(eid_t, g_eid_t);

    dim3 tb(32, 8);

    // ---- prep ----
    k_rowsum<<<NSRC, 256>>>(Xt, sums);
    k_colsum<<<BATCH, 512>>>(Xt, sums + NSRC);
    k_extra<<<32, 256>>>(sums, t_in, extra);
    k_xcat0<<<NTOT, 256>>>(x_s, x_t, extra, xcat_h, xcat_l);
    k_convT<<<dim3(4, K0PAD / 32, 1), tb>>>(lin0_w, 1064, EMBED, EMBED, 0,
                                            WT0_h, WT0_l, K0PAD, 0);
    bgemm<1><<<dim3(1, NTOT / 32, 1), 256, GS_M1>>>(
        xcat_h, xcat_l, K0PAD, 0, WT0_h, WT0_l, K0PAD, 0,
        xin, EMBED, 0, lin0_b, K0PAD);

    k_convS<<<(BATCH * NS * NT / 4 + 255) / 256, 256>>>(Xt, Xh, Xl, BATCH * NS * NT);
    k_convT<<<dim3(16, 16, BATCH), tb>>>(Xt, NS, NT, NT, (long long)NS * NT,
                                         XTh, XTl, NS, (long long)NS * NT);
    k_convT<<<dim3(4, KLPAD / 32, 2), tb>>>(lin_w, 168, EMBED, EMBED, 168 * EMBED,
                                            WTl_h, WTl_l, KLPAD, (long long)EMBED * KLPAD);
    k_convT<<<dim3(4, 8, 75), tb>>>(conv_w, CONV_IN, EMBED, EMBED, (long long)CONV_IN * EMBED,
                                    WrT_h, WrT_l, CONV_IN, (long long)EMBED * CONV_IN);
    k_convT<<<dim3(4, 8, 3), tb>>>(conv_root, CONV_IN, EMBED, EMBED, (long long)CONV_IN * EMBED,
                                   rtT_h, rtT_l, CONV_IN, (long long)EMBED * CONV_IN);
    k_convT<<<dim3(4, FINAL_IN / 32, 1), tb>>>(final_w, FINAL_IN, EMBED, EMBED, 0,
                                               fwT_h, fwT_l, FINAL_IN, 0);
    k_copyx<<<NTOT, 256>>>(x_s, x_t, feat_h, feat_l);
    build_csr(ei_s, off_s, eid_s, cnt, tot);
    build_csr(ei_t, off_t, eid_t, cnt, tot);

    for (int l = 0; l < 3; l++) {
        if (l > 0) {
            k_xcatL<<<NTOT, 192>>>(feat_h, feat_l, extra, xcat_h, xcat_l, l);
            const bf16* wh = WTl_h + (long long)(l - 1) * EMBED * KLPAD;
            const bf16* wl = WTl_l + (long long)(l - 1) * EMBED * KLPAD;
            bgemm<1><<<dim3(1, NTOT / 32, 1), 256, GS_M1>>>(
                xcat_h, xcat_l, KLPAD, 0, wh, wl, KLPAD, 0,
                xin, EMBED, 0, lin_b + (l - 1) * EMBED, KLPAD);
        }
        // xinT (fp32 -> transposed split)
        k_convT<<<dim3(4, 256, 1), tb>>>(xin, NTOT, EMBED, EMBED, 0,
                                         xinT_h, xinT_l, NTOT, 0);
        // fused tgt_msg + src_msg (256 CTAs)
        bgemm_msg<<<dim3(1, 16, 16), 256, GS_M1>>>(Xh, Xl, XTh, XTl, xinT_h, xinT_l, msg);

        k_cat<<<NTOT, 256>>>(xin, msg, cat_h, cat_l);

        // Y = cat @ Wr[l]
        bgemm<4><<<dim3(YW / 128, NTOT / 128, 1), 256, GS_M4>>>(
            cat_h, cat_l, CONV_IN, 0,
            WrT_h + (long long)l * YW * CONV_IN, WrT_l + (long long)l * YW * CONV_IN, CONV_IN, 0,
            Y, YW, 0, nullptr, CONV_IN);
        // rootb = cat @ root + bias
        bgemm<1><<<dim3(1, NTOT / 32, 1), 256, GS_M1>>>(
            cat_h, cat_l, CONV_IN, 0,
            rtT_h + (long long)l * EMBED * CONV_IN, rtT_l + (long long)l * EMBED * CONV_IN, CONV_IN, 0,
            rootb, EMBED, 0, conv_bias + l * EMBED, CONV_IN);

        k_spline_agg<<<NSRC, 128>>>(Y, rootb, off_s, eid_s, ei_s, ea_s,
                                    feat_h + ORI + l * EMBED, feat_l + ORI + l * EMBED);
        k_spline_agg<<<NSRC, 128>>>(Y + (long long)NSRC * YW, rootb + (long long)NSRC * EMBED,
                                    off_t, eid_t, ei_t, ea_t,
                                    feat_h + (long long)NSRC * FINAL_IN + ORI + l * EMBED,
                                    feat_l + (long long)NSRC * FINAL_IN + ORI + l * EMBED);
    }

    // h = feat @ final_w + final_b
    bgemm<1><<<dim3(1, NTOT / 32, 1), 256, GS_M1>>>(
        feat_h, feat_l, FINAL_IN, 0, fwT_h, fwT_l, FINAL_IN, 0,
        hf, EMBED, 0, final_b, FINAL_IN);
    k_convS<<<(NTOT * EMBED / 4 + 255) / 256, 256>>>(hf, hh, hl, NTOT * EMBED);

    // sim = h_s @ h_t^T per batch
    bgemm<2><<<dim3(4, 8, 8), 256, GS_M2>>>(
        hh, hl, EMBED, (long long)NS * EMBED,
        hh + (long long)NSRC * EMBED, hl + (long long)NSRC * EMBED, EMBED, (long long)NT * EMBED,
        out, NT, (long long)NS * NT, nullptr, EMBED);

    k_softmax<<<NSRC, 256>>>(out);
}

// round 9
// speedup vs baseline: 1.4695x; 1.0979x over previous
#include <cuda_runtime.h>
#include <cuda_bf16.h>
#include <math.h>
#include <stdint.h>

// ---------------- problem constants ----------------
#define BATCH 8
#define NS 512
#define NT 512
#define NSRC 4096
#define NTOT 8192
#define NEDGE 32768
#define EMBED 128
#define ORI 1024
#define CONV_IN 256
#define FINAL_IN 1408
#define KK 25
#define YW 3200
#define CHUNK 32
#define NCHUNK 1024
#define K0PAD 1088
#define KLPAD 192

typedef __nv_bfloat16 bf16;

// ---------------- device scratch ----------------
__device__ __align__(16) bf16 g_xcat_h[NTOT * K0PAD];
__device__ __align__(16) bf16 g_xcat_l[NTOT * K0PAD];
__device__ __align__(16) bf16 g_Xh[BATCH * NS * NT];
__device__ __align__(16) bf16 g_Xl[BATCH * NS * NT];
__device__ __align__(16) bf16 g_XTh[BATCH * NS * NT];
__device__ __align__(16) bf16 g_XTl[BATCH * NS * NT];
__device__ __align__(16) bf16 g_xinT_h[EMBED * NTOT];
__device__ __align__(16) bf16 g_xinT_l[EMBED * NTOT];
__device__ __align__(16) bf16 g_cat_h[NTOT * CONV_IN];
__device__ __align__(16) bf16 g_cat_l[NTOT * CONV_IN];
__device__ __align__(16) bf16 g_feat_h[NTOT * FINAL_IN];
__device__ __align__(16) bf16 g_feat_l[NTOT * FINAL_IN];
__device__ __align__(16) bf16 g_hh[NTOT * EMBED];
__device__ __align__(16) bf16 g_hl[NTOT * EMBED];
__device__ __align__(16) bf16 g_WrT_h[3 * YW * CONV_IN];
__device__ __align__(16) bf16 g_WrT_l[3 * YW * CONV_IN];
__device__ __align__(16) bf16 g_WT0_h[EMBED * K0PAD];
__device__ __align__(16) bf16 g_WT0_l[EMBED * K0PAD];
__device__ __align__(16) bf16 g_WTl_h[2 * EMBED * KLPAD];
__device__ __align__(16) bf16 g_WTl_l[2 * EMBED * KLPAD];
__device__ __align__(16) bf16 g_rtT_h[3 * EMBED * CONV_IN];
__device__ __align__(16) bf16 g_rtT_l[3 * EMBED * CONV_IN];
__device__ __align__(16) bf16 g_fwT_h[EMBED * FINAL_IN];
__device__ __align__(16) bf16 g_fwT_l[EMBED * FINAL_IN];
__device__ float g_xin[NTOT * EMBED];
__device__ float g_rootb[NTOT * EMBED];
__device__ float g_Y[NTOT * YW];
__device__ float g_extra[NTOT * 40];
__device__ float g_sum[NTOT];
__device__ int   g_cnt[2 * NCHUNK * 4096];
__device__ int   g_tot[2 * 4096];
__device__ int   g_off[2 * 4097];
__device__ int   g_eid[2 * NEDGE];

// ---------------- helpers ----------------
__device__ __forceinline__ void vsplit(float v, bf16& h, bf16& l) {
    h = __float2bfloat16(v);
    l = __float2bfloat16(v - __bfloat162float(h));
}
__device__ __forceinline__ uint32_t smem_u32(const void* p) {
    uint32_t a;
    asm("{ .reg .u64 t; cvta.to.shared.u64 t, %1; cvt.u32.u64 %0, t; }" : "=r"(a) : "l"(p));
    return a;
}
__device__ __forceinline__ void cp16(uint32_t s, const void* g) {
    asm volatile("cp.async.cg.shared.global [%0], [%1], 16;" :: "r"(s), "l"(g));
}
__device__ __forceinline__ void ldsm4(uint32_t* r, uint32_t a) {
    asm volatile("ldmatrix.sync.aligned.m8n8.x4.shared.b16 {%0,%1,%2,%3}, [%4];"
                 : "=r"(r[0]), "=r"(r[1]), "=r"(r[2]), "=r"(r[3]) : "r"(a));
}
__device__ __forceinline__ void mma16816(float* d, const uint32_t* a, const uint32_t* b) {
    asm volatile("mma.sync.aligned.m16n8k16.row.col.f32.bf16.bf16.f32 "
                 "{%0,%1,%2,%3}, {%4,%5,%6,%7}, {%8,%9}, {%0,%1,%2,%3};"
                 : "+f"(d[0]), "+f"(d[1]), "+f"(d[2]), "+f"(d[3])
                 : "r"(a[0]), "r"(a[1]), "r"(a[2]), "r"(a[3]), "r"(b[0]), "r"(b[1]));
}
__device__ __forceinline__ __nv_bfloat162 pack2(float a, float b) {
    return __floats2bfloat162_rn(a, b);
}

// ======================================================================
// bf16 3-term GEMM core: C = Ah*Bh + Ah*Bl + Al*Bh (+bias), fp32 accum.
// Mainloop identical to R8 (proven). EPI selects the epilogue:
//   EPI=0: plain fp32 C write
//   EPI=1: write C(xin fp32) + xinT hi/lo (transposed split) + cat part1 split
//   EPI=2: read xin via C-ptr; write cat part2 = split(xin - acc)
//   EPI=3: write hi/lo split to E1h/E1l (stride 128)
// ======================================================================
template <int MT, int EPI>
__device__ __forceinline__ void bgemm_core(
    const bf16* __restrict__ Ah, const bf16* __restrict__ Al, int lda,
    const bf16* __restrict__ Bh, const bf16* __restrict__ Bl, int ldb,
    float* __restrict__ C, int ldc, const float* __restrict__ bias,
    int K, int m0, int n0, char* smem,
    bf16* __restrict__ E1h, bf16* __restrict__ E1l,
    bf16* __restrict__ E2h, bf16* __restrict__ E2l)
{
    constexpr int ROWSA = 32 * MT;
    constexpr int SEGSA = ROWSA * 4;
    constexpr int SEGS  = 2 * SEGSA + 1024;
    constexpr int PER   = (SEGS + 255) / 256;
    constexpr int BOFF  = 2 * ROWSA * 80;
    constexpr int STAGE = BOFF + 20480;
    constexpr bool GUARD = (SEGS % 256) != 0;

    const uint32_t sb = smem_u32(smem);
    const int tid = threadIdx.x, wid = tid >> 5, lane = tid & 31;
    const int wm = wid & 1, wn = wid >> 1;

    const bf16* gp[PER];
    uint32_t sd[PER];
#pragma unroll
    for (int i = 0; i < PER; i++) {
        int idx = tid + i * 256;
        gp[i] = nullptr; sd[i] = 0;
        if (!GUARD || idx < SEGS) {
            if (idx < SEGSA) {
                int r = idx >> 2, sg = idx & 3;
                gp[i] = Ah + (long long)(m0 + r) * lda + sg * 8;
                sd[i] = sb + r * 80 + sg * 16;
            } else if (idx < 2 * SEGSA) {
                int j = idx - SEGSA; int r = j >> 2, sg = j & 3;
                gp[i] = Al + (long long)(m0 + r) * lda + sg * 8;
                sd[i] = sb + ROWSA * 80 + r * 80 + sg * 16;
            } else {
                int j = idx - 2 * SEGSA;
                int mat = j >> 9, r = (j >> 2) & 127, sg = j & 3;
                gp[i] = (mat ? Bl : Bh) + (long long)(n0 + r) * ldb + sg * 8;
                sd[i] = sb + BOFF + mat * 10240 + r * 80 + sg * 16;
            }
        }
    }

    const int nch = K >> 5;
    float acc[MT][4][4];
#pragma unroll
    for (int i = 0; i < MT; i++)
#pragma unroll
        for (int j = 0; j < 4; j++)
#pragma unroll
            for (int q = 0; q < 4; q++) acc[i][j][q] = 0.f;

    auto issue = [&](uint32_t bufoff) {
#pragma unroll
        for (int i = 0; i < PER; i++) {
            if (!GUARD || gp[i]) { cp16(sd[i] + bufoff, gp[i]); gp[i] += 32; }
        }
        asm volatile("cp.async.commit_group;");
    };

    issue(0);
    int cur = 0;
    for (int c = 0; c < nch; c++) {
        if (c + 1 < nch) { issue((cur ^ 1) * STAGE); asm volatile("cp.async.wait_group 1;"); }
        else             { asm volatile("cp.async.wait_group 0;"); }
        __syncthreads();

        const uint32_t base   = sb + cur * STAGE;
        const uint32_t alBase = base + ROWSA * 80;
        const uint32_t bhBase = base + BOFF;
        const uint32_t blBase = bhBase + 10240;
        const uint32_t aRow  = (uint32_t)(wm * 16 * MT) + (lane & 15);
        const uint32_t aK    = (lane >> 4) * 16;
        const uint32_t bRow4 = (uint32_t)(wn * 32) + ((lane >> 4) & 1) * 8 + (lane & 7);
        const uint32_t bK4   = ((lane >> 3) & 1) * 16;
#pragma unroll
        for (int s = 0; s < 2; s++) {
            uint32_t bh[4][2], bl[4][2], a[4];
            ldsm4(&bh[0][0], bhBase + bRow4 * 80 + s * 32 + bK4);
            ldsm4(&bh[2][0], bhBase + (bRow4 + 16) * 80 + s * 32 + bK4);
            ldsm4(&bl[0][0], blBase + bRow4 * 80 + s * 32 + bK4);
            ldsm4(&bl[2][0], blBase + (bRow4 + 16) * 80 + s * 32 + bK4);
#pragma unroll
            for (int mt = 0; mt < MT; mt++) {
                ldsm4(a, base + (aRow + mt * 16) * 80 + s * 32 + aK);
#pragma unroll
                for (int nt = 0; nt < 4; nt++) mma16816(acc[mt][nt], a, bh[nt]);
#pragma unroll
                for (int nt = 0; nt < 4; nt++) mma16816(acc[mt][nt], a, bl[nt]);
                ldsm4(a, alBase + (aRow + mt * 16) * 80 + s * 32 + aK);
#pragma unroll
                for (int nt = 0; nt < 4; nt++) mma16816(acc[mt][nt], a, bh[nt]);
            }
        }
        __syncthreads();
        cur ^= 1;
    }

    const int rbase = m0 + wm * 16 * MT + (lane >> 2);
    const int cbase = n0 + wn * 32 + 2 * (lane & 3);
#pragma unroll
    for (int mt = 0; mt < MT; mt++) {
#pragma unroll
        for (int nt = 0; nt < 4; nt++) {
            const int r = rbase + mt * 16, cc = cbase + nt * 8;
            float b0 = 0.f, b1 = 0.f;
            if (bias) { b0 = bias[cc]; b1 = bias[cc + 1]; }
            float e00 = acc[mt][nt][0] + b0, e01 = acc[mt][nt][1] + b1;
            float e10 = acc[mt][nt][2] + b0, e11 = acc[mt][nt][3] + b1;
            if constexpr (EPI == 0) {
                *(float2*)(C + (long long)r * ldc + cc) = make_float2(e00, e01);
                *(float2*)(C + (long long)(r + 8) * ldc + cc) = make_float2(e10, e11);
            } else if constexpr (EPI == 1) {
                // xin fp32
                *(float2*)(C + (long long)r * 128 + cc) = make_float2(e00, e01);
                *(float2*)(C + (long long)(r + 8) * 128 + cc) = make_float2(e10, e11);
                // xinT split (transposed)
                bf16 h, l;
                vsplit(e00, h, l); E1h[(long long)cc * NTOT + r] = h;       E1l[(long long)cc * NTOT + r] = l;
                vsplit(e01, h, l); E1h[(long long)(cc + 1) * NTOT + r] = h; E1l[(long long)(cc + 1) * NTOT + r] = l;
                vsplit(e10, h, l); E1h[(long long)cc * NTOT + r + 8] = h;       E1l[(long long)cc * NTOT + r + 8] = l;
                vsplit(e11, h, l); E1h[(long long)(cc + 1) * NTOT + r + 8] = h; E1l[(long long)(cc + 1) * NTOT + r + 8] = l;
                // cat part1 split
                bf16 h2, l2;
                vsplit(e00, h, l); vsplit(e01, h2, l2);
                *(__nv_bfloat162*)(E2h + (long long)r * CONV_IN + cc) = __nv_bfloat162(h, h2);
                *(__nv_bfloat162*)(E2l + (long long)r * CONV_IN + cc) = __nv_bfloat162(l, l2);
                vsplit(e10, h, l); vsplit(e11, h2, l2);
                *(__nv_bfloat162*)(E2h + (long long)(r + 8) * CONV_IN + cc) = __nv_bfloat162(h, h2);
                *(__nv_bfloat162*)(E2l + (long long)(r + 8) * CONV_IN + cc) = __nv_bfloat162(l, l2);
            } else if constexpr (EPI == 2) {
                // cat part2 = split(xin - msg)
                float2 x0 = *(const float2*)(C + (long long)r * 128 + cc);
                float2 x1 = *(const float2*)(C + (long long)(r + 8) * 128 + cc);
                bf16 h, l, h2, l2;
                vsplit(x0.x - e00, h, l); vsplit(x0.y - e01, h2, l2);
                *(__nv_bfloat162*)(E2h + (long long)r * CONV_IN + cc) = __nv_bfloat162(h, h2);
                *(__nv_bfloat162*)(E2l + (long long)r * CONV_IN + cc) = __nv_bfloat162(l, l2);
                vsplit(x1.x - e10, h, l); vsplit(x1.y - e11, h2, l2);
                *(__nv_bfloat162*)(E2h + (long long)(r + 8) * CONV_IN + cc) = __nv_bfloat162(h, h2);
                *(__nv_bfloat162*)(E2l + (long long)(r + 8) * CONV_IN + cc) = __nv_bfloat162(l, l2);
            } else {
                // split to E1 (stride 128)
                bf16 h, l, h2, l2;
                vsplit(e00, h, l); vsplit(e01, h2, l2);
                *(__nv_bfloat162*)(E1h + (long long)r * 128 + cc) = __nv_bfloat162(h, h2);
                *(__nv_bfloat162*)(E1l + (long long)r * 128 + cc) = __nv_bfloat162(l, l2);
                vsplit(e10, h, l); vsplit(e11, h2, l2);
                *(__nv_bfloat162*)(E1h + (long long)(r + 8) * 128 + cc) = __nv_bfloat162(h, h2);
                *(__nv_bfloat162*)(E1l + (long long)(r + 8) * 128 + cc) = __nv_bfloat162(l, l2);
            }
        }
    }
}

template <int MT>
__global__ void __launch_bounds__(256, 2) bgemm(
    const bf16* __restrict__ Ah, const bf16* __restrict__ Al, int lda, long long sA,
    const bf16* __restrict__ Bh, const bf16* __restrict__ Bl, int ldb, long long sB,
    float* __restrict__ C, int ldc, long long sC,
    const float* __restrict__ bias, int K)
{
    extern __shared__ char smem[];
    bgemm_core<MT, 0>(
        Ah + (long long)blockIdx.z * sA, Al + (long long)blockIdx.z * sA, lda,
        Bh + (long long)blockIdx.z * sB, Bl + (long long)blockIdx.z * sB, ldb,
        C + (long long)blockIdx.z * sC, ldc, bias, K,
        blockIdx.y * 32 * MT, blockIdx.x * 128, smem,
        nullptr, nullptr, nullptr, nullptr);
}

// xin GEMM with fused outputs: xin fp32, xinT split, cat part1 split
__global__ void __launch_bounds__(256, 2) bgemm_xin(
    const bf16* __restrict__ Ah, const bf16* __restrict__ Al, int lda,
    const bf16* __restrict__ Bh, const bf16* __restrict__ Bl, int ldb,
    float* __restrict__ xin, const float* __restrict__ bias, int K,
    bf16* __restrict__ xinT_h, bf16* __restrict__ xinT_l,
    bf16* __restrict__ cat_h, bf16* __restrict__ cat_l)
{
    extern __shared__ char smem[];
    bgemm_core<1, 1>(Ah, Al, lda, Bh, Bl, ldb, xin, 128, bias, K,
                     blockIdx.y * 32, 0, smem, xinT_h, xinT_l, cat_h, cat_l);
}

// fused msg GEMM + cat part2: z<8 -> tgt_msg, z>=8 -> src_msg
__global__ void __launch_bounds__(256, 2) bgemm_msg(
    const bf16* __restrict__ Xh, const bf16* __restrict__ Xl,
    const bf16* __restrict__ XTh, const bf16* __restrict__ XTl,
    const bf16* __restrict__ xinT_h, const bf16* __restrict__ xinT_l,
    float* __restrict__ xin, bf16* __restrict__ cat_h, bf16* __restrict__ cat_l)
{
    extern __shared__ char smem[];
    const int z = blockIdx.z, b = z & 7, sel = z >> 3;
    const bf16* Ah = (sel ? XTh : Xh) + (long long)b * NS * NT;
    const bf16* Al = (sel ? XTl : Xl) + (long long)b * NS * NT;
    const bf16* Bh = xinT_h + (sel ? 0 : NSRC) + b * 512;
    const bf16* Bl = xinT_l + (sel ? 0 : NSRC) + b * 512;
    const long long nodeBase = (long long)(sel ? NSRC : 0) + (long long)b * 512;
    bgemm_core<1, 2>(Ah, Al, 512, Bh, Bl, NTOT,
                     xin + nodeBase * 128, 128, nullptr, 512,
                     blockIdx.y * 32, 0, smem,
                     nullptr, nullptr,
                     cat_h + nodeBase * CONV_IN + 128, cat_l + nodeBase * CONV_IN + 128);
}

// final GEMM with fused split output
__global__ void __launch_bounds__(256, 2) bgemm_fin(
    const bf16* __restrict__ Ah, const bf16* __restrict__ Al, int lda,
    const bf16* __restrict__ Bh, const bf16* __restrict__ Bl, int ldb,
    const float* __restrict__ bias, int K,
    bf16* __restrict__ hh, bf16* __restrict__ hl)
{
    extern __shared__ char smem[];
    bgemm_core<1, 3>(Ah, Al, lda, Bh, Bl, ldb, nullptr, 128, bias, K,
                     blockIdx.y * 32, 0, smem, hh, hl, nullptr, nullptr);
}

// ---------------- transpose + split: fp32 [R][C] -> bf16 [C][Rpad] ----------------
__global__ void k_convT(const float* __restrict__ in, int R, int C, int ldin, long long sIn,
                        bf16* __restrict__ oh, bf16* __restrict__ ol, int Rpad, long long sOut) {
    __shared__ float t[32][33];
    in += (long long)blockIdx.z * sIn;
    oh += (long long)blockIdx.z * sOut;
    ol += (long long)blockIdx.z * sOut;
    int r0 = blockIdx.y * 32, c0 = blockIdx.x * 32;
    for (int i = threadIdx.y; i < 32; i += 8) {
        int r = r0 + i, c = c0 + threadIdx.x;
        t[i][threadIdx.x] = (r < R && c < C) ? in[(long long)r * ldin + c] : 0.f;
    }
    __syncthreads();
    for (int i = threadIdx.y; i < 32; i += 8) {
        int c = c0 + i, r = r0 + threadIdx.x;
        if (c < C && r < Rpad) {
            bf16 h, l; vsplit(t[threadIdx.x][i], h, l);
            oh[(long long)c * Rpad + r] = h;
            ol[(long long)c * Rpad + r] = l;
        }
    }
}
__global__ void k_convS(const float* __restrict__ in, bf16* __restrict__ oh,
                        bf16* __restrict__ ol, int n) {
    int i = (blockIdx.x * 256 + threadIdx.x) * 4;
    if (i >= n) return;
    float4 v = *(const float4*)(in + i);
    __nv_bfloat162 h01 = pack2(v.x, v.y);
    __nv_bfloat162 h23 = pack2(v.z, v.w);
    __nv_bfloat162 l01 = pack2(v.x - __bfloat162float(h01.x), v.y - __bfloat162float(h01.y));
    __nv_bfloat162 l23 = pack2(v.z - __bfloat162float(h23.x), v.w - __bfloat162float(h23.y));
    *(__nv_bfloat162*)(oh + i)     = h01;
    *(__nv_bfloat162*)(oh + i + 2) = h23;
    *(__nv_bfloat162*)(ol + i)     = l01;
    *(__nv_bfloat162*)(ol + i + 2) = l23;
}

// ---------------- misc kernels ----------------
__global__ void k_rowsum(const float* __restrict__ Xt, float* __restrict__ rs) {
    int n = blockIdx.x;
    const float* row = Xt + (long long)n * NT;
    __shared__ float sm[256];
    float s = row[threadIdx.x] + row[threadIdx.x + 256];
    sm[threadIdx.x] = s; __syncthreads();
    for (int st = 128; st > 0; st >>= 1) {
        if (threadIdx.x < st) sm[threadIdx.x] += sm[threadIdx.x + st];
        __syncthreads();
    }
    if (threadIdx.x == 0) rs[n] = sm[0];
}
__global__ void k_colsum(const float* __restrict__ Xt, float* __restrict__ cs) {
    int b = blockIdx.x, t = threadIdx.x;
    float s = 0.f;
    const float* base = Xt + (long long)b * NS * NT + t;
    for (int srow = 0; srow < NS; srow++) s += base[srow * NT];
    cs[b * NT + t] = s;
}
__global__ void k_extra(const float* __restrict__ sums, const float* __restrict__ tvec,
                        float* __restrict__ extra) {
    int n = blockIdx.x * blockDim.x + threadIdx.x;
    if (n >= NTOT) return;
    float x = sums[n] * 0.1f;
    float tb = tvec[(n >> 9) & 7];
    const float c = -1.0233711524418064f;
#pragma unroll
    for (int i = 0; i < 10; i++) {
        float f = expf(c * (float)i);
        float ax = x * f, at = tb * f;
        extra[n * 40 + i]      = sinf(ax);
        extra[n * 40 + 10 + i] = cosf(ax);
        extra[n * 40 + 20 + i] = sinf(at);
        extra[n * 40 + 30 + i] = cosf(at);
    }
}
__global__ void k_copyx(const float* __restrict__ xs, const float* __restrict__ xt,
                        bf16* __restrict__ fh, bf16* __restrict__ fl) {
    int n = blockIdx.x;
    const float* x = (n < NSRC) ? xs + (long long)n * ORI : xt + (long long)(n - NSRC) * ORI;
    int c = threadIdx.x * 4;
    float4 v = *(const float4*)(x + c);
    bf16 h0, l0, h1, l1, h2, l2, h3, l3;
    vsplit(v.x, h0, l0); vsplit(v.y, h1, l1);
    vsplit(v.z, h2, l2); vsplit(v.w, h3, l3);
    long long o = (long long)n * FINAL_IN + c;
    fh[o] = h0; fh[o + 1] = h1; fh[o + 2] = h2; fh[o + 3] = h3;
    fl[o] = l0; fl[o + 1] = l1; fl[o + 2] = l2; fl[o + 3] = l3;
}
__global__ void k_xcat0(const float* __restrict__ xs, const float* __restrict__ xt,
                        const float* __restrict__ extra,
                        bf16* __restrict__ oh, bf16* __restrict__ ol) {
    int n = blockIdx.x;
    const float* x = (n < NSRC) ? xs + (long long)n * ORI : xt + (long long)(n - NSRC) * ORI;
    const float* ex = extra + n * 40;
    for (int q = threadIdx.x; q < K0PAD / 4; q += 256) {
        int c = q * 4;
        float4 v;
        if (c < ORI)        v = *(const float4*)(x + c);
        else if (c < 1064)  v = *(const float4*)(ex + (c - ORI));
        else                v = make_float4(0.f, 0.f, 0.f, 0.f);
        __nv_bfloat162 h01 = pack2(v.x, v.y);
        __nv_bfloat162 h23 = pack2(v.z, v.w);
        __nv_bfloat162 l01 = pack2(v.x - __bfloat162float(h01.x), v.y - __bfloat162float(h01.y));
        __nv_bfloat162 l23 = pack2(v.z - __bfloat162float(h23.x), v.w - __bfloat162float(h23.y));
        long long o = (long long)n * K0PAD + c;
        *(__nv_bfloat162*)(oh + o)     = h01;
        *(__nv_bfloat162*)(oh + o + 2) = h23;
        *(__nv_bfloat162*)(ol + o)     = l01;
        *(__nv_bfloat162*)(ol + o + 2) = l23;
    }
}
__global__ void k_xcatL(const bf16* __restrict__ fh, const bf16* __restrict__ fl,
                        const float* __restrict__ extra,
                        bf16* __restrict__ oh, bf16* __restrict__ ol, int l) {
    int n = blockIdx.x, c = threadIdx.x;   // 192 threads
    bf16 h = __float2bfloat16(0.f), lo = h;
    if (c < 128) {
        long long o = (long long)n * FINAL_IN + ORI + (l - 1) * EMBED + c;
        h = fh[o]; lo = fl[o];
    } else if (c < 168) {
        vsplit(extra[n * 40 + (c - 128)], h, lo);
    }
    oh[(long long)n * KLPAD + c] = h;
    ol[(long long)n * KLPAD + c] = lo;
}

// ----- stable CSR build, both sides fused (cnt layout: [side][chunk][dst]) -----
__global__ void k_count2(const int* __restrict__ eis, const int* __restrict__ eit,
                         int* __restrict__ cnt) {
    int blk = blockIdx.x;
    int side = blk >> 7;
    int e = (blk & 127) * 256 + threadIdx.x;
    const int* ei = side ? eit : eis;
    int d = ei[NEDGE + e];
    atomicAdd(&cnt[side * (NCHUNK * 4096) + (e >> 5) * 4096 + d], 1);
}
__global__ void k_colscan2(int* __restrict__ cnt, int* __restrict__ tot) {
    int idx = blockIdx.x * 256 + threadIdx.x;
    int side = idx >> 12, d = idx & 4095;
    int* base = cnt + side * (NCHUNK * 4096);
    int run = 0;
    for (int c = 0; c < NCHUNK; c++) {
        int v = base[c * 4096 + d];
        base[c * 4096 + d] = run;
        run += v;
    }
    tot[side * 4096 + d] = run;
}
__global__ void k_scan2(const int* __restrict__ tot, int* __restrict__ off) {
    __shared__ int s[1024];
    int side = blockIdx.x;
    tot += side * 4096; off += side * 4097;
    int tid = threadIdx.x;
    int v[4]; int sum = 0;
#pragma unroll
    for (int i = 0; i < 4; i++) { v[i] = tot[tid * 4 + i]; sum += v[i]; }
    s[tid] = sum; __syncthreads();
    for (int d = 1; d < 1024; d <<= 1) {
        int x = (tid >= d) ? s[tid - d] : 0;
        __syncthreads();
        s[tid] += x;
        __syncthreads();
    }
    int run = (tid == 0) ? 0 : s[tid - 1];
#pragma unroll
    for (int i = 0; i < 4; i++) { off[tid * 4 + i] = run; run += v[i]; }
    if (tid == 1023) off[4096] = run;
}
__global__ void k_place2(const int* __restrict__ eis, const int* __restrict__ eit,
                         const int* __restrict__ off, int* __restrict__ cnt,
                         int* __restrict__ eid) {
    int idx = blockIdx.x * 256 + threadIdx.x;
    int side = idx >> 10, c = idx & 1023;
    const int* ei = side ? eit : eis;
    const int* offs = off + side * 4097;
    int* cnts = cnt + side * (NCHUNK * 4096);
    int* eids = eid + side * NEDGE;
    for (int j = 0; j < CHUNK; j++) {
        int e = c * CHUNK + j;
        int d = ei[NEDGE + e];
        int r = cnts[c * 4096 + d];
        cnts[c * 4096 + d] = r + 1;
        eids[offs[d] + r] = e;
    }
}

// ----- spline gather + mean + root + tanh -> feat hi/lo -----
__global__ void k_spline_agg(const float* __restrict__ Y, const float* __restrict__ rootb,
                             const int* __restrict__ off, const int* __restrict__ eid,
                             const int* __restrict__ ei, const float* __restrict__ ea,
                             bf16* __restrict__ oh, bf16* __restrict__ ol) {
    int n = blockIdx.x, d = threadIdx.x;       // 128
    int beg = off[n], end = off[n + 1];

    auto contrib = [&](int e) -> float {
        int src = ei[e];
        float v0 = ea[e * 2] * 4.f, v1 = ea[e * 2 + 1] * 4.f;
        float l0 = floorf(v0), l1 = floorf(v1);
        float f0 = v0 - l0, f1 = v1 - l1;
        int i0 = (int)l0, i1 = (int)l1;
        const float* Ys = Y + (long long)src * YW;
        float r = 0.f;
#pragma unroll
        for (int s1 = 0; s1 < 2; s1++)
#pragma unroll
            for (int s0 = 0; s0 < 2; s0++) {
                int a0 = min(max(i0 + s0, 0), 4);
                int a1 = min(max(i1 + s1, 0), 4);
                float w = (s0 ? f0 : 1.f - f0) * (s1 ? f1 : 1.f - f1);
                r += w * Ys[(a0 + 5 * a1) * EMBED + d];
            }
        return r;
    };

    float acc0 = 0.f, acc1 = 0.f;
    int j = beg;
    for (; j + 2 <= end; j += 2) {
        acc0 += contrib(eid[j]);
        acc1 += contrib(eid[j + 1]);
    }
    if (j < end) acc0 += contrib(eid[j]);
    float acc = acc0 + acc1;

    float deg = (float)(end - beg);
    acc = acc / fmaxf(deg, 1.f);
    float v = tanhf(acc + rootb[n * EMBED + d]);
    bf16 h, l; vsplit(v, h, l);
    oh[(long long)n * FINAL_IN + d] = h;
    ol[(long long)n * FINAL_IN + d] = l;
}

__global__ void k_softmax(float* __restrict__ out) {
    int r = blockIdx.x;
    float* row = out + (long long)r * NT;
    __shared__ float sm[256];
    int tid = threadIdx.x;
    float a = row[tid], b = row[tid + 256];
    sm[tid] = fmaxf(a, b); __syncthreads();
    for (int s = 128; s > 0; s >>= 1) {
        if (tid < s) sm[tid] = fmaxf(sm[tid], sm[tid + s]);
        __syncthreads();
    }
    float mx = sm[0]; __syncthreads();
    float ea = expf(a - mx), eb = expf(b - mx);
    sm[tid] = ea + eb; __syncthreads();
    for (int s = 128; s > 0; s >>= 1) {
        if (tid < s) sm[tid] += sm[tid + s];
        __syncthreads();
    }
    float inv = 1.f / sm[0];
    row[tid] = ea * inv;
    row[tid + 256] = eb * inv;
}

// ---------------- host ----------------
#define STG(MT) (2 * (2 * (MT) * 32 * 80 + 20480))
#define GS_M1 STG(1)   // 51200
#define GS_M2 STG(2)   // 61440
#define GS_M4 STG(4)   // 81920

#define GETSYM(v, s) cudaGetSymbolAddress((void**)&v, s)

extern "C" void kernel_launch(void* const* d_in, const int* in_sizes, int n_in,
                              void* d_out, int out_size) {
    const float* t_in      = (const float*)d_in[0];
    const float* Xt        = (const float*)d_in[1];
    const float* x_s       = (const float*)d_in[2];
    const float* x_t       = (const float*)d_in[3];
    const float* ea_s      = (const float*)d_in[4];
    const float* ea_t      = (const float*)d_in[5];
    const float* lin0_w    = (const float*)d_in[6];
    const float* lin0_b    = (const float*)d_in[7];
    const float* lin_w     = (const float*)d_in[8];
    const float* lin_b     = (const float*)d_in[9];
    const float* conv_w    = (const float*)d_in[10];
    const float* conv_root = (const float*)d_in[11];
    const float* conv_bias = (const float*)d_in[12];
    const float* final_w   = (const float*)d_in[13];
    const float* final_b   = (const float*)d_in[14];
    const int*   ei_s      = (const int*)d_in[15];
    const int*   ei_t      = (const int*)d_in[16];
    float* out = (float*)d_out;

    cudaFuncSetAttribute(bgemm<1>, cudaFuncAttributeMaxDynamicSharedMemorySize, GS_M1);
    cudaFuncSetAttribute(bgemm<2>, cudaFuncAttributeMaxDynamicSharedMemorySize, GS_M2);
    cudaFuncSetAttribute(bgemm<4>, cudaFuncAttributeMaxDynamicSharedMemorySize, GS_M4);
    cudaFuncSetAttribute(bgemm_xin, cudaFuncAttributeMaxDynamicSharedMemorySize, GS_M1);
    cudaFuncSetAttribute(bgemm_msg, cudaFuncAttributeMaxDynamicSharedMemorySize, GS_M1);
    cudaFuncSetAttribute(bgemm_fin, cudaFuncAttributeMaxDynamicSharedMemorySize, GS_M1);

    bf16 *xcat_h, *xcat_l, *Xh, *Xl, *XTh, *XTl, *xinT_h, *xinT_l, *cat_h, *cat_l;
    bf16 *feat_h, *feat_l, *hh, *hl, *WrT_h, *WrT_l, *WT0_h, *WT0_l, *WTl_h, *WTl_l;
    bf16 *rtT_h, *rtT_l, *fwT_h, *fwT_l;
    float *xin, *rootb, *Y, *extra, *sums;
    int *cnt, *tot, *off, *eid;
    GETSYM(xcat_h, g_xcat_h); GETSYM(xcat_l, g_xcat_l);
    GETSYM(Xh, g_Xh); GETSYM(Xl, g_Xl); GETSYM(XTh, g_XTh); GETSYM(XTl, g_XTl);
    GETSYM(xinT_h, g_xinT_h); GETSYM(xinT_l, g_xinT_l);
    GETSYM(cat_h, g_cat_h); GETSYM(cat_l, g_cat_l);
    GETSYM(feat_h, g_feat_h); GETSYM(feat_l, g_feat_l);
    GETSYM(hh, g_hh); GETSYM(hl, g_hl);
    GETSYM(WrT_h, g_WrT_h); GETSYM(WrT_l, g_WrT_l);
    GETSYM(WT0_h, g_WT0_h); GETSYM(WT0_l, g_WT0_l);
    GETSYM(WTl_h, g_WTl_h); GETSYM(WTl_l, g_WTl_l);
    GETSYM(rtT_h, g_rtT_h); GETSYM(rtT_l, g_rtT_l);
    GETSYM(fwT_h, g_fwT_h); GETSYM(fwT_l, g_fwT_l);
    GETSYM(xin, g_xin); GETSYM(rootb, g_rootb);
    GETSYM(Y, g_Y); GETSYM(extra, g_extra); GETSYM(sums, g_sum);
    GETSYM(cnt, g_cnt); GETSYM(tot, g_tot);
    GETSYM(off, g_off); GETSYM(eid, g_eid);

    dim3 tb(32, 8);

    // ---- prep ----
    k_rowsum<<<NSRC, 256>>>(Xt, sums);
    k_colsum<<<BATCH, 512>>>(Xt, sums + NSRC);
    k_extra<<<32, 256>>>(sums, t_in, extra);
    k_xcat0<<<NTOT, 256>>>(x_s, x_t, extra, xcat_h, xcat_l);
    k_convT<<<dim3(4, K0PAD / 32, 1), tb>>>(lin0_w, 1064, EMBED, EMBED, 0,
                                            WT0_h, WT0_l, K0PAD, 0);
    k_convS<<<(BATCH * NS * NT / 4 + 255) / 256, 256>>>(Xt, Xh, Xl, BATCH * NS * NT);
    k_convT<<<dim3(16, 16, BATCH), tb>>>(Xt, NS, NT, NT, (long long)NS * NT,
                                         XTh, XTl, NS, (long long)NS * NT);
    k_convT<<<dim3(4, KLPAD / 32, 2), tb>>>(lin_w, 168, EMBED, EMBED, 168 * EMBED,
                                            WTl_h, WTl_l, KLPAD, (long long)EMBED * KLPAD);
    k_convT<<<dim3(4, 8, 75), tb>>>(conv_w, CONV_IN, EMBED, EMBED, (long long)CONV_IN * EMBED,
                                    WrT_h, WrT_l, CONV_IN, (long long)EMBED * CONV_IN);
    k_convT<<<dim3(4, 8, 3), tb>>>(conv_root, CONV_IN, EMBED, EMBED, (long long)CONV_IN * EMBED,
                                   rtT_h, rtT_l, CONV_IN, (long long)EMBED * CONV_IN);
    k_convT<<<dim3(4, FINAL_IN / 32, 1), tb>>>(final_w, FINAL_IN, EMBED, EMBED, 0,
                                               fwT_h, fwT_l, FINAL_IN, 0);
    k_copyx<<<NTOT, 256>>>(x_s, x_t, feat_h, feat_l);

    // ---- CSR build, both sides fused ----
    cudaMemsetAsync(cnt, 0, 2 * NCHUNK * 4096 * sizeof(int));
    k_count2<<<256, 256>>>(ei_s, ei_t, cnt);
    k_colscan2<<<32, 256>>>(cnt, tot);
    k_scan2<<<2, 1024>>>(tot, off);
    k_place2<<<8, 256>>>(ei_s, ei_t, off, cnt, eid);

    for (int l = 0; l < 3; l++) {
        if (l == 0) {
            bgemm_xin<<<dim3(1, NTOT / 32, 1), 256, GS_M1>>>(
                xcat_h, xcat_l, K0PAD, WT0_h, WT0_l, K0PAD,
                xin, lin0_b, K0PAD, xinT_h, xinT_l, cat_h, cat_l);
        } else {
            k_xcatL<<<NTOT, 192>>>(feat_h, feat_l, extra, xcat_h, xcat_l, l);
            const bf16* wh = WTl_h + (long long)(l - 1) * EMBED * KLPAD;
            const bf16* wl = WTl_l + (long long)(l - 1) * EMBED * KLPAD;
            bgemm_xin<<<dim3(1, NTOT / 32, 1), 256, GS_M1>>>(
                xcat_h, xcat_l, KLPAD, wh, wl, KLPAD,
                xin, lin_b + (l - 1) * EMBED, KLPAD, xinT_h, xinT_l, cat_h, cat_l);
        }
        // fused tgt_msg + src_msg -> cat part2
        bgemm_msg<<<dim3(1, 16, 16), 256, GS_M1>>>(Xh, Xl, XTh, XTl, xinT_h, xinT_l,
                                                   xin, cat_h, cat_l);

        // Y = cat @ Wr[l]
        bgemm<4><<<dim3(YW / 128, NTOT / 128, 1), 256, GS_M4>>>(
            cat_h, cat_l, CONV_IN, 0,
            WrT_h + (long long)l * YW * CONV_IN, WrT_l + (long long)l * YW * CONV_IN, CONV_IN, 0,
            Y, YW, 0, nullptr, CONV_IN);
        // rootb = cat @ root + bias
        bgemm<1><<<dim3(1, NTOT / 32, 1), 256, GS_M1>>>(
            cat_h, cat_l, CONV_IN, 0,
            rtT_h + (long long)l * EMBED * CONV_IN, rtT_l + (long long)l * EMBED * CONV_IN, CONV_IN, 0,
            rootb, EMBED, 0, conv_bias + l * EMBED, CONV_IN);

        k_spline_agg<<<NSRC, 128>>>(Y, rootb, off, eid, ei_s, ea_s,
                                    feat_h + ORI + l * EMBED, feat_l + ORI + l * EMBED);
        k_spline_agg<<<NSRC, 128>>>(Y + (long long)NSRC * YW, rootb + (long long)NSRC * EMBED,
                                    off + 4097, eid + NEDGE, ei_t, ea_t,
                                    feat_h + (long long)NSRC * FINAL_IN + ORI + l * EMBED,
                                    feat_l + (long long)NSRC * FINAL_IN + ORI + l * EMBED);
    }

    // h = feat @ final_w + final_b (split output fused)
    bgemm_fin<<<dim3(1, NTOT / 32, 1), 256, GS_M1>>>(
        feat_h, feat_l, FINAL_IN, fwT_h, fwT_l, FINAL_IN,
        final_b, FINAL_IN, hh, hl);

    // sim = h_s @ h_t^T per batch
    bgemm<2><<<dim3(4, 8, 8), 256, GS_M2>>>(
        hh, hl, EMBED, (long long)NS * EMBED,
        hh + (long long)NSRC * EMBED, hl + (long long)NSRC * EMBED, EMBED, (long long)NT * EMBED,
        out, NT, (long long)NS * NT, nullptr, EMBED);

    k_softmax<<<NSRC, 256>>>(out);
}

// round 10
// speedup vs baseline: 1.5226x; 1.0361x over previous
#include <cuda_runtime.h>
#include <cuda_bf16.h>
#include <math.h>
#include <stdint.h>

// ---------------- problem constants ----------------
#define BATCH 8
#define NS 512
#define NT 512
#define NSRC 4096
#define NTOT 8192
#define NEDGE 32768
#define EMBED 128
#define ORI 1024
#define CONV_IN 256
#define FINAL_IN 1408
#define KK 25
#define YW 3200
#define YW2 3328            // 3200 conv cols + 128 root cols
#define CHUNK 32
#define NCHUNK 1024
#define K0PAD 1088
#define KLPAD 192

typedef __nv_bfloat16 bf16;

// ---------------- device scratch ----------------
__device__ __align__(16) bf16 g_xcat_h[NTOT * K0PAD];
__device__ __align__(16) bf16 g_xcat_l[NTOT * K0PAD];
__device__ __align__(16) bf16 g_Xh[BATCH * NS * NT];
__device__ __align__(16) bf16 g_Xl[BATCH * NS * NT];
__device__ __align__(16) bf16 g_XTh[BATCH * NS * NT];
__device__ __align__(16) bf16 g_XTl[BATCH * NS * NT];
__device__ __align__(16) bf16 g_xinT_h[EMBED * NTOT];
__device__ __align__(16) bf16 g_xinT_l[EMBED * NTOT];
__device__ __align__(16) bf16 g_cat_h[NTOT * CONV_IN];
__device__ __align__(16) bf16 g_cat_l[NTOT * CONV_IN];
__device__ __align__(16) bf16 g_feat_h[NTOT * FINAL_IN];
__device__ __align__(16) bf16 g_feat_l[NTOT * FINAL_IN];
__device__ __align__(16) bf16 g_hh[NTOT * EMBED];
__device__ __align__(16) bf16 g_hl[NTOT * EMBED];
__device__ __align__(16) bf16 g_WrT_h[3 * YW2 * CONV_IN];
__device__ __align__(16) bf16 g_WrT_l[3 * YW2 * CONV_IN];
__device__ __align__(16) bf16 g_WT0_h[EMBED * K0PAD];
__device__ __align__(16) bf16 g_WT0_l[EMBED * K0PAD];
__device__ __align__(16) bf16 g_WTl_h[2 * EMBED * KLPAD];
__device__ __align__(16) bf16 g_WTl_l[2 * EMBED * KLPAD];
__device__ __align__(16) bf16 g_fwT_h[EMBED * FINAL_IN];
__device__ __align__(16) bf16 g_fwT_l[EMBED * FINAL_IN];
__device__ float g_xin[NTOT * EMBED];
__device__ float g_Y[NTOT * YW2];
__device__ float g_extra[NTOT * 40];
__device__ float g_sum[NTOT];
__device__ float g_bias2[3 * YW2];
__device__ unsigned int g_cnt[2 * NCHUNK * 2048];   // packed u16 x2 per word
__device__ int   g_tot[2 * 4096];
__device__ int   g_off[2 * 4097];
__device__ int   g_eid[2 * NEDGE];

// ---------------- helpers ----------------
__device__ __forceinline__ void vsplit(float v, bf16& h, bf16& l) {
    h = __float2bfloat16(v);
    l = __float2bfloat16(v - __bfloat162float(h));
}
__device__ __forceinline__ uint32_t smem_u32(const void* p) {
    uint32_t a;
    asm("{ .reg .u64 t; cvta.to.shared.u64 t, %1; cvt.u32.u64 %0, t; }" : "=r"(a) : "l"(p));
    return a;
}
__device__ __forceinline__ void cp16(uint32_t s, const void* g) {
    asm volatile("cp.async.cg.shared.global [%0], [%1], 16;" :: "r"(s), "l"(g));
}
__device__ __forceinline__ void ldsm4(uint32_t* r, uint32_t a) {
    asm volatile("ldmatrix.sync.aligned.m8n8.x4.shared.b16 {%0,%1,%2,%3}, [%4];"
                 : "=r"(r[0]), "=r"(r[1]), "=r"(r[2]), "=r"(r[3]) : "r"(a));
}
__device__ __forceinline__ void mma16816(float* d, const uint32_t* a, const uint32_t* b) {
    asm volatile("mma.sync.aligned.m16n8k16.row.col.f32.bf16.bf16.f32 "
                 "{%0,%1,%2,%3}, {%4,%5,%6,%7}, {%8,%9}, {%0,%1,%2,%3};"
                 : "+f"(d[0]), "+f"(d[1]), "+f"(d[2]), "+f"(d[3])
                 : "r"(a[0]), "r"(a[1]), "r"(a[2]), "r"(a[3]), "r"(b[0]), "r"(b[1]));
}
__device__ __forceinline__ __nv_bfloat162 pack2(float a, float b) {
    return __floats2bfloat162_rn(a, b);
}

// ======================================================================
// bf16 3-term GEMM core: C = Ah*Bh + Ah*Bl + Al*Bh (+bias), fp32 accum.
// Mainloop proven (R8). EPI selects the epilogue:
//   EPI=0: plain fp32 C write
//   EPI=1: write C(xin fp32) + xinT hi/lo (transposed split) + cat part1 split
//   EPI=2: read xin via C-ptr; write cat part2 = split(xin - acc)
//   EPI=3: write hi/lo split to E1h/E1l (stride 128)
// ======================================================================
template <int MT, int EPI>
__device__ __forceinline__ void bgemm_core(
    const bf16* __restrict__ Ah, const bf16* __restrict__ Al, int lda,
    const bf16* __restrict__ Bh, const bf16* __restrict__ Bl, int ldb,
    float* __restrict__ C, int ldc, const float* __restrict__ bias,
    int K, int m0, int n0, char* smem,
    bf16* __restrict__ E1h, bf16* __restrict__ E1l,
    bf16* __restrict__ E2h, bf16* __restrict__ E2l)
{
    constexpr int ROWSA = 32 * MT;
    constexpr int SEGSA = ROWSA * 4;
    constexpr int SEGS  = 2 * SEGSA + 1024;
    constexpr int PER   = (SEGS + 255) / 256;
    constexpr int BOFF  = 2 * ROWSA * 80;
    constexpr int STAGE = BOFF + 20480;
    constexpr bool GUARD = (SEGS % 256) != 0;

    const uint32_t sb = smem_u32(smem);
    const int tid = threadIdx.x, wid = tid >> 5, lane = tid & 31;
    const int wm = wid & 1, wn = wid >> 1;

    const bf16* gp[PER];
    uint32_t sd[PER];
#pragma unroll
    for (int i = 0; i < PER; i++) {
        int idx = tid + i * 256;
        gp[i] = nullptr; sd[i] = 0;
        if (!GUARD || idx < SEGS) {
            if (idx < SEGSA) {
                int r = idx >> 2, sg = idx & 3;
                gp[i] = Ah + (long long)(m0 + r) * lda + sg * 8;
                sd[i] = sb + r * 80 + sg * 16;
            } else if (idx < 2 * SEGSA) {
                int j = idx - SEGSA; int r = j >> 2, sg = j & 3;
                gp[i] = Al + (long long)(m0 + r) * lda + sg * 8;
                sd[i] = sb + ROWSA * 80 + r * 80 + sg * 16;
            } else {
                int j = idx - 2 * SEGSA;
                int mat = j >> 9, r = (j >> 2) & 127, sg = j & 3;
                gp[i] = (mat ? Bl : Bh) + (long long)(n0 + r) * ldb + sg * 8;
                sd[i] = sb + BOFF + mat * 10240 + r * 80 + sg * 16;
            }
        }
    }

    const int nch = K >> 5;
    float acc[MT][4][4];
#pragma unroll
    for (int i = 0; i < MT; i++)
#pragma unroll
        for (int j = 0; j < 4; j++)
#pragma unroll
            for (int q = 0; q < 4; q++) acc[i][j][q] = 0.f;

    auto issue = [&](uint32_t bufoff) {
#pragma unroll
        for (int i = 0; i < PER; i++) {
            if (!GUARD || gp[i]) { cp16(sd[i] + bufoff, gp[i]); gp[i] += 32; }
        }
        asm volatile("cp.async.commit_group;");
    };

    issue(0);
    int cur = 0;
    for (int c = 0; c < nch; c++) {
        if (c + 1 < nch) { issue((cur ^ 1) * STAGE); asm volatile("cp.async.wait_group 1;"); }
        else             { asm volatile("cp.async.wait_group 0;"); }
        __syncthreads();

        const uint32_t base   = sb + cur * STAGE;
        const uint32_t alBase = base + ROWSA * 80;
        const uint32_t bhBase = base + BOFF;
        const uint32_t blBase = bhBase + 10240;
        const uint32_t aRow  = (uint32_t)(wm * 16 * MT) + (lane & 15);
        const uint32_t aK    = (lane >> 4) * 16;
        const uint32_t bRow4 = (uint32_t)(wn * 32) + ((lane >> 4) & 1) * 8 + (lane & 7);
        const uint32_t bK4   = ((lane >> 3) & 1) * 16;
#pragma unroll
        for (int s = 0; s < 2; s++) {
            uint32_t bh[4][2], bl[4][2], a[4];
            ldsm4(&bh[0][0], bhBase + bRow4 * 80 + s * 32 + bK4);
            ldsm4(&bh[2][0], bhBase + (bRow4 + 16) * 80 + s * 32 + bK4);
            ldsm4(&bl[0][0], blBase + bRow4 * 80 + s * 32 + bK4);
            ldsm4(&bl[2][0], blBase + (bRow4 + 16) * 80 + s * 32 + bK4);
#pragma unroll
            for (int mt = 0; mt < MT; mt++) {
                ldsm4(a, base + (aRow + mt * 16) * 80 + s * 32 + aK);
#pragma unroll
                for (int nt = 0; nt < 4; nt++) mma16816(acc[mt][nt], a, bh[nt]);
#pragma unroll
                for (int nt = 0; nt < 4; nt++) mma16816(acc[mt][nt], a, bl[nt]);
                ldsm4(a, alBase + (aRow + mt * 16) * 80 + s * 32 + aK);
#pragma unroll
                for (int nt = 0; nt < 4; nt++) mma16816(acc[mt][nt], a, bh[nt]);
            }
        }
        __syncthreads();
        cur ^= 1;
    }

    const int rbase = m0 + wm * 16 * MT + (lane >> 2);
    const int cbase = n0 + wn * 32 + 2 * (lane & 3);
#pragma unroll
    for (int mt = 0; mt < MT; mt++) {
#pragma unroll
        for (int nt = 0; nt < 4; nt++) {
            const int r = rbase + mt * 16, cc = cbase + nt * 8;
            float b0 = 0.f, b1 = 0.f;
            if (bias) { b0 = bias[cc]; b1 = bias[cc + 1]; }
            float e00 = acc[mt][nt][0] + b0, e01 = acc[mt][nt][1] + b1;
            float e10 = acc[mt][nt][2] + b0, e11 = acc[mt][nt][3] + b1;
            if constexpr (EPI == 0) {
                *(float2*)(C + (long long)r * ldc + cc) = make_float2(e00, e01);
                *(float2*)(C + (long long)(r + 8) * ldc + cc) = make_float2(e10, e11);
            } else if constexpr (EPI == 1) {
                *(float2*)(C + (long long)r * 128 + cc) = make_float2(e00, e01);
                *(float2*)(C + (long long)(r + 8) * 128 + cc) = make_float2(e10, e11);
                bf16 h, l;
                vsplit(e00, h, l); E1h[(long long)cc * NTOT + r] = h;       E1l[(long long)cc * NTOT + r] = l;
                vsplit(e01, h, l); E1h[(long long)(cc + 1) * NTOT + r] = h; E1l[(long long)(cc + 1) * NTOT + r] = l;
                vsplit(e10, h, l); E1h[(long long)cc * NTOT + r + 8] = h;       E1l[(long long)cc * NTOT + r + 8] = l;
                vsplit(e11, h, l); E1h[(long long)(cc + 1) * NTOT + r + 8] = h; E1l[(long long)(cc + 1) * NTOT + r + 8] = l;
                bf16 h2, l2;
                vsplit(e00, h, l); vsplit(e01, h2, l2);
                *(__nv_bfloat162*)(E2h + (long long)r * CONV_IN + cc) = __nv_bfloat162(h, h2);
                *(__nv_bfloat162*)(E2l + (long long)r * CONV_IN + cc) = __nv_bfloat162(l, l2);
                vsplit(e10, h, l); vsplit(e11, h2, l2);
                *(__nv_bfloat162*)(E2h + (long long)(r + 8) * CONV_IN + cc) = __nv_bfloat162(h, h2);
                *(__nv_bfloat162*)(E2l + (long long)(r + 8) * CONV_IN + cc) = __nv_bfloat162(l, l2);
            } else if constexpr (EPI == 2) {
                float2 x0 = *(const float2*)(C + (long long)r * 128 + cc);
                float2 x1 = *(const float2*)(C + (long long)(r + 8) * 128 + cc);
                bf16 h, l, h2, l2;
                vsplit(x0.x - e00, h, l); vsplit(x0.y - e01, h2, l2);
                *(__nv_bfloat162*)(E2h + (long long)r * CONV_IN + cc) = __nv_bfloat162(h, h2);
                *(__nv_bfloat162*)(E2l + (long long)r * CONV_IN + cc) = __nv_bfloat162(l, l2);
                vsplit(x1.x - e10, h, l); vsplit(x1.y - e11, h2, l2);
                *(__nv_bfloat162*)(E2h + (long long)(r + 8) * CONV_IN + cc) = __nv_bfloat162(h, h2);
                *(__nv_bfloat162*)(E2l + (long long)(r + 8) * CONV_IN + cc) = __nv_bfloat162(l, l2);
            } else {
                bf16 h, l, h2, l2;
                vsplit(e00, h, l); vsplit(e01, h2, l2);
                *(__nv_bfloat162*)(E1h + (long long)r * 128 + cc) = __nv_bfloat162(h, h2);
                *(__nv_bfloat162*)(E1l + (long long)r * 128 + cc) = __nv_bfloat162(l, l2);
                vsplit(e10, h, l); vsplit(e11, h2, l2);
                *(__nv_bfloat162*)(E1h + (long long)(r + 8) * 128 + cc) = __nv_bfloat162(h, h2);
                *(__nv_bfloat162*)(E1l + (long long)(r + 8) * 128 + cc) = __nv_bfloat162(l, l2);
            }
        }
    }
}

template <int MT>
__global__ void __launch_bounds__(256, 2) bgemm(
    const bf16* __restrict__ Ah, const bf16* __restrict__ Al, int lda, long long sA,
    const bf16* __restrict__ Bh, const bf16* __restrict__ Bl, int ldb, long long sB,
    float* __restrict__ C, int ldc, long long sC,
    const float* __restrict__ bias, int K)
{
    extern __shared__ char smem[];
    bgemm_core<MT, 0>(
        Ah + (long long)blockIdx.z * sA, Al + (long long)blockIdx.z * sA, lda,
        Bh + (long long)blockIdx.z * sB, Bl + (long long)blockIdx.z * sB, ldb,
        C + (long long)blockIdx.z * sC, ldc, bias, K,
        blockIdx.y * 32 * MT, blockIdx.x * 128, smem,
        nullptr, nullptr, nullptr, nullptr);
}

__global__ void __launch_bounds__(256, 2) bgemm_xin(
    const bf16* __restrict__ Ah, const bf16* __restrict__ Al, int lda,
    const bf16* __restrict__ Bh, const bf16* __restrict__ Bl, int ldb,
    float* __restrict__ xin, const float* __restrict__ bias, int K,
    bf16* __restrict__ xinT_h, bf16* __restrict__ xinT_l,
    bf16* __restrict__ cat_h, bf16* __restrict__ cat_l)
{
    extern __shared__ char smem[];
    bgemm_core<1, 1>(Ah, Al, lda, Bh, Bl, ldb, xin, 128, bias, K,
                     blockIdx.y * 32, 0, smem, xinT_h, xinT_l, cat_h, cat_l);
}

__global__ void __launch_bounds__(256, 2) bgemm_msg(
    const bf16* __restrict__ Xh, const bf16* __restrict__ Xl,
    const bf16* __restrict__ XTh, const bf16* __restrict__ XTl,
    const bf16* __restrict__ xinT_h, const bf16* __restrict__ xinT_l,
    float* __restrict__ xin, bf16* __restrict__ cat_h, bf16* __restrict__ cat_l)
{
    extern __shared__ char smem[];
    const int z = blockIdx.z, b = z & 7, sel = z >> 3;
    const bf16* Ah = (sel ? XTh : Xh) + (long long)b * NS * NT;
    const bf16* Al = (sel ? XTl : Xl) + (long long)b * NS * NT;
    const bf16* Bh = xinT_h + (sel ? 0 : NSRC) + b * 512;
    const bf16* Bl = xinT_l + (sel ? 0 : NSRC) + b * 512;
    const long long nodeBase = (long long)(sel ? NSRC : 0) + (long long)b * 512;
    bgemm_core<1, 2>(Ah, Al, 512, Bh, Bl, NTOT,
                     xin + nodeBase * 128, 128, nullptr, 512,
                     blockIdx.y * 32, 0, smem,
                     nullptr, nullptr,
                     cat_h + nodeBase * CONV_IN + 128, cat_l + nodeBase * CONV_IN + 128);
}

__global__ void __launch_bounds__(256, 2) bgemm_fin(
    const bf16* __restrict__ Ah, const bf16* __restrict__ Al, int lda,
    const bf16* __restrict__ Bh, const bf16* __restrict__ Bl, int ldb,
    const float* __restrict__ bias, int K,
    bf16* __restrict__ hh, bf16* __restrict__ hl)
{
    extern __shared__ char smem[];
    bgemm_core<1, 3>(Ah, Al, lda, Bh, Bl, ldb, nullptr, 128, bias, K,
                     blockIdx.y * 32, 0, smem, hh, hl, nullptr, nullptr);
}

// ---------------- transpose + split ----------------
__global__ void k_convT(const float* __restrict__ in, int R, int C, int ldin, long long sIn,
                        bf16* __restrict__ oh, bf16* __restrict__ ol, int Rpad, long long sOut) {
    __shared__ float t[32][33];
    in += (long long)blockIdx.z * sIn;
    oh += (long long)blockIdx.z * sOut;
    ol += (long long)blockIdx.z * sOut;
    int r0 = blockIdx.y * 32, c0 = blockIdx.x * 32;
    for (int i = threadIdx.y; i < 32; i += 8) {
        int r = r0 + i, c = c0 + threadIdx.x;
        t[i][threadIdx.x] = (r < R && c < C) ? in[(long long)r * ldin + c] : 0.f;
    }
    __syncthreads();
    for (int i = threadIdx.y; i < 32; i += 8) {
        int c = c0 + i, r = r0 + threadIdx.x;
        if (c < C && r < Rpad) {
            bf16 h, l; vsplit(t[threadIdx.x][i], h, l);
            oh[(long long)c * Rpad + r] = h;
            ol[(long long)c * Rpad + r] = l;
        }
    }
}
__global__ void k_convS(const float* __restrict__ in, bf16* __restrict__ oh,
                        bf16* __restrict__ ol, int n) {
    int i = (blockIdx.x * 256 + threadIdx.x) * 4;
    if (i >= n) return;
    float4 v = *(const float4*)(in + i);
    __nv_bfloat162 h01 = pack2(v.x, v.y);
    __nv_bfloat162 h23 = pack2(v.z, v.w);
    __nv_bfloat162 l01 = pack2(v.x - __bfloat162float(h01.x), v.y - __bfloat162float(h01.y));
    __nv_bfloat162 l23 = pack2(v.z - __bfloat162float(h23.x), v.w - __bfloat162float(h23.y));
    *(__nv_bfloat162*)(oh + i)     = h01;
    *(__nv_bfloat162*)(oh + i + 2) = h23;
    *(__nv_bfloat162*)(ol + i)     = l01;
    *(__nv_bfloat162*)(ol + i + 2) = l23;
}

// ---------------- misc ----------------
__global__ void k_rowsum(const float* __restrict__ Xt, float* __restrict__ rs) {
    int n = blockIdx.x;
    const float* row = Xt + (long long)n * NT;
    __shared__ float sm[256];
    float s = row[threadIdx.x] + row[threadIdx.x + 256];
    sm[threadIdx.x] = s; __syncthreads();
    for (int st = 128; st > 0; st >>= 1) {
        if (threadIdx.x < st) sm[threadIdx.x] += sm[threadIdx.x + st];
        __syncthreads();
    }
    if (threadIdx.x == 0) rs[n] = sm[0];
}
__global__ void k_colsum(const float* __restrict__ Xt, float* __restrict__ cs) {
    int b = blockIdx.x, t = threadIdx.x;
    float s = 0.f;
    const float* base = Xt + (long long)b * NS * NT + t;
    for (int srow = 0; srow < NS; srow++) s += base[srow * NT];
    cs[b * NT + t] = s;
}
__global__ void k_extra(const float* __restrict__ sums, const float* __restrict__ tvec,
                        float* __restrict__ extra) {
    int n = blockIdx.x * blockDim.x + threadIdx.x;
    if (n >= NTOT) return;
    float x = sums[n] * 0.1f;
    float tb = tvec[(n >> 9) & 7];
    const float c = -1.0233711524418064f;
#pragma unroll
    for (int i = 0; i < 10; i++) {
        float f = expf(c * (float)i);
        float ax = x * f, at = tb * f;
        extra[n * 40 + i]      = sinf(ax);
        extra[n * 40 + 10 + i] = cosf(ax);
        extra[n * 40 + 20 + i] = sinf(at);
        extra[n * 40 + 30 + i] = cosf(at);
    }
}
__global__ void k_copyx(const float* __restrict__ xs, const float* __restrict__ xt,
                        bf16* __restrict__ fh, bf16* __restrict__ fl) {
    int n = blockIdx.x;
    const float* x = (n < NSRC) ? xs + (long long)n * ORI : xt + (long long)(n - NSRC) * ORI;
    int c = threadIdx.x * 4;
    float4 v = *(const float4*)(x + c);
    bf16 h0, l0, h1, l1, h2, l2, h3, l3;
    vsplit(v.x, h0, l0); vsplit(v.y, h1, l1);
    vsplit(v.z, h2, l2); vsplit(v.w, h3, l3);
    long long o = (long long)n * FINAL_IN + c;
    fh[o] = h0; fh[o + 1] = h1; fh[o + 2] = h2; fh[o + 3] = h3;
    fl[o] = l0; fl[o + 1] = l1; fl[o + 2] = l2; fl[o + 3] = l3;
}
__global__ void k_xcat0(const float* __restrict__ xs, const float* __restrict__ xt,
                        const float* __restrict__ extra,
                        bf16* __restrict__ oh, bf16* __restrict__ ol) {
    int n = blockIdx.x;
    const float* x = (n < NSRC) ? xs + (long long)n * ORI : xt + (long long)(n - NSRC) * ORI;
    const float* ex = extra + n * 40;
    for (int q = threadIdx.x; q < K0PAD / 4; q += 256) {
        int c = q * 4;
        float4 v;
        if (c < ORI)        v = *(const float4*)(x + c);
        else if (c < 1064)  v = *(const float4*)(ex + (c - ORI));
        else                v = make_float4(0.f, 0.f, 0.f, 0.f);
        __nv_bfloat162 h01 = pack2(v.x, v.y);
        __nv_bfloat162 h23 = pack2(v.z, v.w);
        __nv_bfloat162 l01 = pack2(v.x - __bfloat162float(h01.x), v.y - __bfloat162float(h01.y));
        __nv_bfloat162 l23 = pack2(v.z - __bfloat162float(h23.x), v.w - __bfloat162float(h23.y));
        long long o = (long long)n * K0PAD + c;
        *(__nv_bfloat162*)(oh + o)     = h01;
        *(__nv_bfloat162*)(oh + o + 2) = h23;
        *(__nv_bfloat162*)(ol + o)     = l01;
        *(__nv_bfloat162*)(ol + o + 2) = l23;
    }
}
__global__ void k_xcatL(const bf16* __restrict__ fh, const bf16* __restrict__ fl,
                        const float* __restrict__ extra,
                        bf16* __restrict__ oh, bf16* __restrict__ ol, int l) {
    int n = blockIdx.x, c = threadIdx.x;   // 192 threads
    bf16 h = __float2bfloat16(0.f), lo = h;
    if (c < 128) {
        long long o = (long long)n * FINAL_IN + ORI + (l - 1) * EMBED + c;
        h = fh[o]; lo = fl[o];
    } else if (c < 168) {
        vsplit(extra[n * 40 + (c - 128)], h, lo);
    }
    oh[(long long)n * KLPAD + c] = h;
    ol[(long long)n * KLPAD + c] = lo;
}
__global__ void k_bias2(const float* __restrict__ cb, float* __restrict__ b2) {
    int i = blockIdx.x * 256 + threadIdx.x;
    if (i >= 3 * YW2) return;
    int l = i / YW2, c = i % YW2;
    b2[i] = (c >= YW) ? cb[l * EMBED + (c - YW)] : 0.f;
}

// ----- stable CSR build, packed u16 counters ([side][chunk][dst/2] u32 words) -----
__global__ void k_count2(const int* __restrict__ eis, const int* __restrict__ eit,
                         unsigned int* __restrict__ cnt) {
    int blk = blockIdx.x;
    int side = blk >> 7;
    int e = (blk & 127) * 256 + threadIdx.x;
    const int* ei = side ? eit : eis;
    int d = ei[NEDGE + e];
    atomicAdd(&cnt[side * (NCHUNK * 2048) + (e >> 5) * 2048 + (d >> 1)],
              1u << ((d & 1) * 16));
}
__global__ void k_colscan2(unsigned int* __restrict__ cnt, int* __restrict__ tot) {
    int idx = blockIdx.x * 256 + threadIdx.x;     // 4096 threads: [side][pair]
    int side = idx >> 11, p = idx & 2047;
    unsigned int* base = cnt + side * (NCHUNK * 2048);
    unsigned int run0 = 0, run1 = 0;
    for (int c = 0; c < NCHUNK; c++) {
        unsigned int v = base[c * 2048 + p];
        base[c * 2048 + p] = run0 | (run1 << 16);
        run0 += v & 0xFFFFu;
        run1 += v >> 16;
    }
    tot[side * 4096 + 2 * p]     = (int)run0;
    tot[side * 4096 + 2 * p + 1] = (int)run1;
}
__global__ void k_scan2(const int* __restrict__ tot, int* __restrict__ off) {
    __shared__ int s[1024];
    int side = blockIdx.x;
    tot += side * 4096; off += side * 4097;
    int tid = threadIdx.x;
    int v[4]; int sum = 0;
#pragma unroll
    for (int i = 0; i < 4; i++) { v[i] = tot[tid * 4 + i]; sum += v[i]; }
    s[tid] = sum; __syncthreads();
    for (int d = 1; d < 1024; d <<= 1) {
        int x = (tid >= d) ? s[tid - d] : 0;
        __syncthreads();
        s[tid] += x;
        __syncthreads();
    }
    int run = (tid == 0) ? 0 : s[tid - 1];
#pragma unroll
    for (int i = 0; i < 4; i++) { off[tid * 4 + i] = run; run += v[i]; }
    if (tid == 1023) off[4096] = run;
}
__global__ void k_place2(const int* __restrict__ eis, const int* __restrict__ eit,
                         const int* __restrict__ off, unsigned int* __restrict__ cnt,
                         int* __restrict__ eid) {
    int idx = blockIdx.x * 256 + threadIdx.x;     // 2048 threads: [side][chunk]
    int side = idx >> 10, c = idx & 1023;
    const int* ei = side ? eit : eis;
    const int* offs = off + side * 4097;
    unsigned short* cnt16 = (unsigned short*)cnt + (long long)(side * NCHUNK + c) * 4096;
    int* eids = eid + side * NEDGE;
    for (int j = 0; j < CHUNK; j++) {
        int e = c * CHUNK + j;
        int d = ei[NEDGE + e];
        int r = cnt16[d];
        cnt16[d] = (unsigned short)(r + 1);
        eids[offs[d] + r] = e;
    }
}

// ----- spline gather (both sides) + mean + root + tanh -> feat hi/lo -----
__global__ void k_spline2(const float* __restrict__ Y,
                          const int* __restrict__ off, const int* __restrict__ eid,
                          const int* __restrict__ ei_s, const int* __restrict__ ei_t,
                          const float* __restrict__ ea_s, const float* __restrict__ ea_t,
                          bf16* __restrict__ fh, bf16* __restrict__ fl, int l) {
    int n = blockIdx.x, d = threadIdx.x;       // NTOT blocks x 128
    int side = n >> 12, nl = n & 4095;
    const int* offs = off + side * 4097;
    const int* eids = eid + side * NEDGE;
    const int* ei = side ? ei_t : ei_s;
    const float* ea = side ? ea_t : ea_s;
    const float* Yside = Y + (long long)side * NSRC * YW2;
    int beg = offs[nl], end = offs[nl + 1];

    auto contrib = [&](int e) -> float {
        int src = ei[e];
        float v0 = ea[e * 2] * 4.f, v1 = ea[e * 2 + 1] * 4.f;
        float l0 = floorf(v0), l1 = floorf(v1);
        float f0 = v0 - l0, f1 = v1 - l1;
        int i0 = (int)l0, i1 = (int)l1;
        const float* Ys = Yside + (long long)src * YW2;
        float r = 0.f;
#pragma unroll
        for (int s1 = 0; s1 < 2; s1++)
#pragma unroll
            for (int s0 = 0; s0 < 2; s0++) {
                int a0 = min(max(i0 + s0, 0), 4);
                int a1 = min(max(i1 + s1, 0), 4);
                float w = (s0 ? f0 : 1.f - f0) * (s1 ? f1 : 1.f - f1);
                r += w * Ys[(a0 + 5 * a1) * EMBED + d];
            }
        return r;
    };

    float acc0 = 0.f, acc1 = 0.f;
    int j = beg;
    for (; j + 2 <= end; j += 2) {
        acc0 += contrib(eids[j]);
        acc1 += contrib(eids[j + 1]);
    }
    if (j < end) acc0 += contrib(eids[j]);
    float acc = acc0 + acc1;

    float deg = (float)(end - beg);
    acc = acc / fmaxf(deg, 1.f);
    float rootb = Y[(long long)n * YW2 + YW + d];
    float v = tanhf(acc + rootb);
    bf16 h, lo; vsplit(v, h, lo);
    fh[(long long)n * FINAL_IN + ORI + l * EMBED + d] = h;
    fl[(long long)n * FINAL_IN + ORI + l * EMBED + d] = lo;
}

__global__ void k_softmax(float* __restrict__ out) {
    int r = blockIdx.x;
    float* row = out + (long long)r * NT;
    __shared__ float sm[256];
    int tid = threadIdx.x;
    float a = row[tid], b = row[tid + 256];
    sm[tid] = fmaxf(a, b); __syncthreads();
    for (int s = 128; s > 0; s >>= 1) {
        if (tid < s) sm[tid] = fmaxf(sm[tid], sm[tid + s]);
        __syncthreads();
    }
    float mx = sm[0]; __syncthreads();
    float ea = expf(a - mx), eb = expf(b - mx);
    sm[tid] = ea + eb; __syncthreads();
    for (int s = 128; s > 0; s >>= 1) {
        if (tid < s) sm[tid] += sm[tid + s];
        __syncthreads();
    }
    float inv = 1.f / sm[0];
    row[tid] = ea * inv;
    row[tid + 256] = eb * inv;
}

// ---------------- host ----------------
#define STG(MT) (2 * (2 * (MT) * 32 * 80 + 20480))
#define GS_M1 STG(1)
#define GS_M2 STG(2)
#define GS_M4 STG(4)

#define GETSYM(v, s) cudaGetSymbolAddress((void**)&v, s)

extern "C" void kernel_launch(void* const* d_in, const int* in_sizes, int n_in,
                              void* d_out, int out_size) {
    const float* t_in      = (const float*)d_in[0];
    const float* Xt        = (const float*)d_in[1];
    const float* x_s       = (const float*)d_in[2];
    const float* x_t       = (const float*)d_in[3];
    const float* ea_s      = (const float*)d_in[4];
    const float* ea_t      = (const float*)d_in[5];
    const float* lin0_w    = (const float*)d_in[6];
    const float* lin0_b    = (const float*)d_in[7];
    const float* lin_w     = (const float*)d_in[8];
    const float* lin_b     = (const float*)d_in[9];
    const float* conv_w    = (const float*)d_in[10];
    const float* conv_root = (const float*)d_in[11];
    const float* conv_bias = (const float*)d_in[12];
    const float* final_w   = (const float*)d_in[13];
    const float* final_b   = (const float*)d_in[14];
    const int*   ei_s      = (const int*)d_in[15];
    const int*   ei_t      = (const int*)d_in[16];
    float* out = (float*)d_out;

    cudaFuncSetAttribute(bgemm<2>, cudaFuncAttributeMaxDynamicSharedMemorySize, GS_M2);
    cudaFuncSetAttribute(bgemm<4>, cudaFuncAttributeMaxDynamicSharedMemorySize, GS_M4);
    cudaFuncSetAttribute(bgemm_xin, cudaFuncAttributeMaxDynamicSharedMemorySize, GS_M1);
    cudaFuncSetAttribute(bgemm_msg, cudaFuncAttributeMaxDynamicSharedMemorySize, GS_M1);
    cudaFuncSetAttribute(bgemm_fin, cudaFuncAttributeMaxDynamicSharedMemorySize, GS_M1);

    bf16 *xcat_h, *xcat_l, *Xh, *Xl, *XTh, *XTl, *xinT_h, *xinT_l, *cat_h, *cat_l;
    bf16 *feat_h, *feat_l, *hh, *hl, *WrT_h, *WrT_l, *WT0_h, *WT0_l, *WTl_h, *WTl_l;
    bf16 *fwT_h, *fwT_l;
    float *xin, *Y, *extra, *sums, *bias2;
    unsigned int *cnt;
    int *tot, *off, *eid;
    GETSYM(xcat_h, g_xcat_h); GETSYM(xcat_l, g_xcat_l);
    GETSYM(Xh, g_Xh); GETSYM(Xl, g_Xl); GETSYM(XTh, g_XTh); GETSYM(XTl, g_XTl);
    GETSYM(xinT_h, g_xinT_h); GETSYM(xinT_l, g_xinT_l);
    GETSYM(cat_h, g_cat_h); GETSYM(cat_l, g_cat_l);
    GETSYM(feat_h, g_feat_h); GETSYM(feat_l, g_feat_l);
    GETSYM(hh, g_hh); GETSYM(hl, g_hl);
    GETSYM(WrT_h, g_WrT_h); GETSYM(WrT_l, g_WrT_l);
    GETSYM(WT0_h, g_WT0_h); GETSYM(WT0_l, g_WT0_l);
    GETSYM(WTl_h, g_WTl_h); GETSYM(WTl_l, g_WTl_l);
    GETSYM(fwT_h, g_fwT_h); GETSYM(fwT_l, g_fwT_l);
    GETSYM(xin, g_xin); GETSYM(Y, g_Y);
    GETSYM(extra, g_extra); GETSYM(sums, g_sum); GETSYM(bias2, g_bias2);
    GETSYM(cnt, g_cnt); GETSYM(tot, g_tot);
    GETSYM(off, g_off); GETSYM(eid, g_eid);

    dim3 tb(32, 8);

    // ---- prep ----
    k_rowsum<<<NSRC, 256>>>(Xt, sums);
    k_colsum<<<BATCH, 512>>>(Xt, sums + NSRC);
    k_extra<<<32, 256>>>(sums, t_in, extra);
    k_xcat0<<<NTOT, 256>>>(x_s, x_t, extra, xcat_h, xcat_l);
    k_convT<<<dim3(4, K0PAD / 32, 1), tb>>>(lin0_w, 1064, EMBED, EMBED, 0,
                                            WT0_h, WT0_l, K0PAD, 0);
    k_convS<<<(BATCH * NS * NT / 4 + 255) / 256, 256>>>(Xt, Xh, Xl, BATCH * NS * NT);
    k_convT<<<dim3(16, 16, BATCH), tb>>>(Xt, NS, NT, NT, (long long)NS * NT,
                                         XTh, XTl, NS, (long long)NS * NT);
    k_convT<<<dim3(4, KLPAD / 32, 2), tb>>>(lin_w, 168, EMBED, EMBED, 168 * EMBED,
                                            WTl_h, WTl_l, KLPAD, (long long)EMBED * KLPAD);
    // conv_w per layer into [3][3328][256] (first 3200 rows)
    for (int l = 0; l < 3; l++)
        k_convT<<<dim3(4, 8, KK), tb>>>(conv_w + (long long)l * KK * CONV_IN * EMBED,
                                        CONV_IN, EMBED, EMBED, (long long)CONV_IN * EMBED,
                                        WrT_h + (long long)l * YW2 * CONV_IN,
                                        WrT_l + (long long)l * YW2 * CONV_IN,
                                        CONV_IN, (long long)EMBED * CONV_IN);
    // conv_root into rows [3200..3328) of each layer
    k_convT<<<dim3(4, 8, 3), tb>>>(conv_root, CONV_IN, EMBED, EMBED, (long long)CONV_IN * EMBED,
                                   WrT_h + (long long)YW * CONV_IN,
                                   WrT_l + (long long)YW * CONV_IN,
                                   CONV_IN, (long long)YW2 * CONV_IN);
    k_convT<<<dim3(4, FINAL_IN / 32, 1), tb>>>(final_w, FINAL_IN, EMBED, EMBED, 0,
                                               fwT_h, fwT_l, FINAL_IN, 0);
    k_bias2<<<(3 * YW2 + 255) / 256, 256>>>(conv_bias, bias2);
    k_copyx<<<NTOT, 256>>>(x_s, x_t, feat_h, feat_l);

    // ---- CSR build (u16 packed counters) ----
    cudaMemsetAsync(cnt, 0, 2 * NCHUNK * 2048 * sizeof(unsigned int));
    k_count2<<<256, 256>>>(ei_s, ei_t, cnt);
    k_colscan2<<<16, 256>>>(cnt, tot);
    k_scan2<<<2, 1024>>>(tot, off);
    k_place2<<<8, 256>>>(ei_s, ei_t, off, cnt, eid);

    for (int l = 0; l < 3; l++) {
        if (l == 0) {
            bgemm_xin<<<dim3(1, NTOT / 32, 1), 256, GS_M1>>>(
                xcat_h, xcat_l, K0PAD, WT0_h, WT0_l, K0PAD,
                xin, lin0_b, K0PAD, xinT_h, xinT_l, cat_h, cat_l);
        } else {
            k_xcatL<<<NTOT, 192>>>(feat_h, feat_l, extra, xcat_h, xcat_l, l);
            const bf16* wh = WTl_h + (long long)(l - 1) * EMBED * KLPAD;
            const bf16* wl = WTl_l + (long long)(l - 1) * EMBED * KLPAD;
            bgemm_xin<<<dim3(1, NTOT / 32, 1), 256, GS_M1>>>(
                xcat_h, xcat_l, KLPAD, wh, wl, KLPAD,
                xin, lin_b + (l - 1) * EMBED, KLPAD, xinT_h, xinT_l, cat_h, cat_l);
        }
        bgemm_msg<<<dim3(1, 16, 16), 256, GS_M1>>>(Xh, Xl, XTh, XTl, xinT_h, xinT_l,
                                                   xin, cat_h, cat_l);

        // Y (+rootb columns) = cat @ [Wr | root], bias = [0 | conv_bias]
        bgemm<4><<<dim3(YW2 / 128, NTOT / 128, 1), 256, GS_M4>>>(
            cat_h, cat_l, CONV_IN, 0,
            WrT_h + (long long)l * YW2 * CONV_IN, WrT_l + (long long)l * YW2 * CONV_IN, CONV_IN, 0,
            Y, YW2, 0, bias2 + l * YW2, CONV_IN);

        k_spline2<<<NTOT, 128>>>(Y, off, eid, ei_s, ei_t, ea_s, ea_t, feat_h, feat_l, l);
    }

    bgemm_fin<<<dim3(1, NTOT / 32, 1), 256, GS_M1>>>(
        feat_h, feat_l, FINAL_IN, fwT_h, fwT_l, FINAL_IN,
        final_b, FINAL_IN, hh, hl);

    bgemm<2><<<dim3(4, 8, 8), 256, GS_M2>>>(
        hh, hl, EMBED, (long long)NS * EMBED,
        hh + (long long)NSRC * EMBED, hl + (long long)NSRC * EMBED, EMBED, (long long)NT * EMBED,
        out, NT, (long long)NS * NT, nullptr, EMBED);

    k_softmax<<<NSRC, 256>>>(out);
}